// round 1
// baseline (speedup 1.0000x reference)
#include <cuda_runtime.h>
#include <math.h>

#define Bsz 1024
#define Dm 1024
#define NH 16
#define DHd 64
#define SEQ 50
#define NOUT 1000
#define LNEPS 1e-5f

// ---------------- scratch (device globals; no allocations allowed) ----------
__device__ float g_pe[SEQ * Dm];            // sinusoidal pos-emb table
__device__ float g_n[Bsz * SEQ * Dm];       // LN1 output, all tokens (210MB)
__device__ float g_tok0[Bsz * Dm];          // token-0 row pre-attention
__device__ float g_tok0p[Bsz * Dm];         // token-0 row after +attention
__device__ float g_n0[Bsz * Dm];            // LN2 output
__device__ float g_final[Bsz * Dm];         // after MLP residual

// ---------------- helpers ----------------------------------------------------
__device__ __forceinline__ float block_reduce_sum256(float v, float* red) {
    int tid = threadIdx.x, lane = tid & 31, w = tid >> 5;
    #pragma unroll
    for (int o = 16; o > 0; o >>= 1) v += __shfl_down_sync(0xffffffffu, v, o);
    if (lane == 0) red[w] = v;
    __syncthreads();
    if (tid < 8) {
        float x = red[tid];
        #pragma unroll
        for (int o = 4; o > 0; o >>= 1) x += __shfl_down_sync(0xffu, x, o);
        if (tid == 0) red[0] = x;
    }
    __syncthreads();
    float r = red[0];
    __syncthreads();
    return r;
}

// ---------------- K0: pos-emb table ------------------------------------------
__global__ void pe_kernel() {
    int s = blockIdx.x;
    for (int d = threadIdx.x; d < Dm; d += blockDim.x) {
        float expo = (float)(d & ~1);
        float denom = powf(10000.0f, expo / (float)Dm);
        float ang = (float)s / denom;
        g_pe[s * Dm + d] = (d & 1) ? cosf(ang) : sinf(ang);
    }
}

// ---------------- K1: patch-embed + pos-emb + LN1 (fused) --------------------
// grid (SEQ, Bsz), 256 threads. Writes g_n for all rows; g_tok0 for s==0.
__global__ __launch_bounds__(256) void embed_ln1_kernel(
    const float* __restrict__ x, const float* __restrict__ cls,
    const float* __restrict__ Wp, const float* __restrict__ lw,
    const float* __restrict__ lb)
{
    int s = blockIdx.x, b = blockIdx.y, tid = threadIdx.x;
    __shared__ float patch[16];
    __shared__ float red[32];
    if (s > 0 && tid < 16) {
        int pi = s - 1, i = pi / 7, j = pi % 7, r = tid >> 2, c = tid & 3;
        patch[tid] = x[b * 784 + (i * 4 + r) * 28 + (j * 4 + c)];
    }
    __syncthreads();
    float vals[4];
    #pragma unroll
    for (int u = 0; u < 4; u++) {
        int d = tid + 256 * u;
        float t;
        if (s == 0) {
            t = cls[d];
        } else {
            t = 0.f;
            const float* wr = &Wp[d * 16];
            #pragma unroll
            for (int p = 0; p < 16; p++) t += patch[p] * wr[p];
        }
        t += g_pe[s * Dm + d];
        vals[u] = t;
        if (s == 0) g_tok0[b * Dm + d] = t;
    }
    float lsum = vals[0] + vals[1] + vals[2] + vals[3];
    float mu = block_reduce_sum256(lsum, red) * (1.0f / (float)Dm);
    float lsq = 0.f;
    #pragma unroll
    for (int u = 0; u < 4; u++) { float dv = vals[u] - mu; lsq += dv * dv; }
    float var = block_reduce_sum256(lsq, red) * (1.0f / (float)Dm);
    float rstd = rsqrtf(var + LNEPS);
    float* nrow = &g_n[(size_t)(b * SEQ + s) * Dm];
    #pragma unroll
    for (int u = 0; u < 4; u++) {
        int d = tid + 256 * u;
        nrow[d] = (vals[u] - mu) * rstd * lw[d] + lb[d];
    }
}

// ---------------- K2: algebraic attention, query row 0 only ------------------
// grid (NH, Bsz), 128 threads.
//   q0 = Wq x0 + bq
//   sc_s = 32 * ((Wk^T q0) . x_s + q0.bk)     (K projection eliminated)
//   p = softmax(sc); c = sum_s p_s x_s
//   out = Wv c + bv                            (V projection eliminated)
//   tok0' = tok0 + out
__global__ __launch_bounds__(128) void attn_kernel(
    const float* __restrict__ Wq, const float* __restrict__ bq,
    const float* __restrict__ Wk, const float* __restrict__ bk,
    const float* __restrict__ Wv, const float* __restrict__ bv)
{
    int h = blockIdx.x, b = blockIdx.y, tid = threadIdx.x;
    __shared__ float xs[SEQ * DHd];
    __shared__ float q0[DHd], tv[DHd], cv[DHd];
    __shared__ float sc[SEQ];
    __shared__ float s_qbk;

    const float* nbase = &g_n[(size_t)b * SEQ * Dm + h * DHd];
    for (int i = tid; i < SEQ * DHd; i += 128) {
        int s = i >> 6, d = i & 63;
        xs[i] = nbase[s * Dm + d];
    }
    __syncthreads();

    if (tid < DHd) {
        float a = bq[h * DHd + tid];
        const float* wr = &Wq[(h * DHd + tid) * DHd];
        #pragma unroll 8
        for (int d = 0; d < DHd; d++) a += wr[d] * xs[d];
        q0[tid] = a;
    }
    __syncthreads();

    if (tid < 32) {  // q0 . bk
        float a = q0[tid] * bk[h * DHd + tid] + q0[tid + 32] * bk[h * DHd + tid + 32];
        #pragma unroll
        for (int o = 16; o > 0; o >>= 1) a += __shfl_down_sync(0xffffffffu, a, o);
        if (tid == 0) s_qbk = a;
    }
    if (tid < DHd) {  // tv = Wk^T q0
        float a = 0.f;
        for (int e = 0; e < DHd; e++) a += q0[e] * Wk[(h * DHd + e) * DHd + tid];
        tv[tid] = a;
    }
    __syncthreads();

    if (tid < SEQ) {
        float a = s_qbk;
        const float* xr = &xs[tid * DHd];
        #pragma unroll 8
        for (int d = 0; d < DHd; d++) a += tv[d] * xr[d];
        sc[tid] = a * 32.0f;  // * sqrt(D), D=1024
    }
    __syncthreads();

    if (tid < 32) {  // softmax over 50
        float v1 = sc[tid];
        float v2 = (tid + 32 < SEQ) ? sc[tid + 32] : -INFINITY;
        float m = fmaxf(v1, v2);
        #pragma unroll
        for (int o = 16; o > 0; o >>= 1) m = fmaxf(m, __shfl_xor_sync(0xffffffffu, m, o));
        float e1 = expf(v1 - m);
        float e2 = (tid + 32 < SEQ) ? expf(v2 - m) : 0.f;
        float ss = e1 + e2;
        #pragma unroll
        for (int o = 16; o > 0; o >>= 1) ss += __shfl_xor_sync(0xffffffffu, ss, o);
        float inv = 1.0f / ss;
        sc[tid] = e1 * inv;
        if (tid + 32 < SEQ) sc[tid + 32] = e2 * inv;
    }
    __syncthreads();

    if (tid < DHd) {  // c = sum_s p_s x_s
        float a = 0.f;
        #pragma unroll 10
        for (int s = 0; s < SEQ; s++) a += sc[s] * xs[s * DHd + tid];
        cv[tid] = a;
    }
    __syncthreads();

    if (tid < DHd) {  // out = Wv c + bv ; residual with tok0
        float a = bv[h * DHd + tid];
        const float* wr = &Wv[(h * DHd + tid) * DHd];
        #pragma unroll 8
        for (int d = 0; d < DHd; d++) a += wr[d] * cv[d];
        int idx = b * Dm + h * DHd + tid;
        g_tok0p[idx] = g_tok0[idx] + a;
    }
}

// ---------------- K3: LN2 on token-0 row -------------------------------------
__global__ __launch_bounds__(256) void ln2_kernel(
    const float* __restrict__ lw, const float* __restrict__ lb)
{
    int b = blockIdx.x, tid = threadIdx.x;
    __shared__ float red[32];
    float vals[4];
    #pragma unroll
    for (int u = 0; u < 4; u++) vals[u] = g_tok0p[b * Dm + tid + 256 * u];
    float mu = block_reduce_sum256(vals[0] + vals[1] + vals[2] + vals[3], red) * (1.0f / (float)Dm);
    float lsq = 0.f;
    #pragma unroll
    for (int u = 0; u < 4; u++) { float dv = vals[u] - mu; lsq += dv * dv; }
    float var = block_reduce_sum256(lsq, red) * (1.0f / (float)Dm);
    float rstd = rsqrtf(var + LNEPS);
    #pragma unroll
    for (int u = 0; u < 4; u++) {
        int d = tid + 256 * u;
        g_n0[b * Dm + d] = (vals[u] - mu) * rstd * lw[d] + lb[d];
    }
}

// ---------------- K4/K5: tiled fp32 GEMM, C = A * Bw^T + bias (+ Res) --------
// A: MxK row-major, Bw: NxK row-major, C/Res: MxN. 64x64 tile, BK=16, 256 thr.
template <bool HAS_RES>
__global__ __launch_bounds__(256) void gemm_nt_kernel(
    const float* __restrict__ A, const float* __restrict__ Bw,
    const float* __restrict__ bias, const float* __restrict__ Res,
    float* __restrict__ C, int M, int N, int K)
{
    __shared__ float As[16][65];
    __shared__ float Bs[16][65];
    int m0 = blockIdx.y * 64, n0 = blockIdx.x * 64;
    int tid = threadIdx.x;
    int tx = tid & 15, ty = tid >> 4;
    int lk = tid & 15, lr = tid >> 4;
    float acc[4][4] = {};
    for (int k0 = 0; k0 < K; k0 += 16) {
        #pragma unroll
        for (int it = 0; it < 4; it++) {
            int r = lr + 16 * it;
            As[lk][r] = A[(size_t)(m0 + r) * K + k0 + lk];
            int n = n0 + r;
            Bs[lk][r] = (n < N) ? Bw[(size_t)n * K + k0 + lk] : 0.f;
        }
        __syncthreads();
        #pragma unroll
        for (int k = 0; k < 16; k++) {
            float ar[4], br[4];
            #pragma unroll
            for (int i = 0; i < 4; i++) ar[i] = As[k][ty * 4 + i];
            #pragma unroll
            for (int j = 0; j < 4; j++) br[j] = Bs[k][tx * 4 + j];
            #pragma unroll
            for (int i = 0; i < 4; i++)
                #pragma unroll
                for (int j = 0; j < 4; j++) acc[i][j] += ar[i] * br[j];
        }
        __syncthreads();
    }
    #pragma unroll
    for (int i = 0; i < 4; i++) {
        int m = m0 + ty * 4 + i;
        #pragma unroll
        for (int j = 0; j < 4; j++) {
            int n = n0 + tx * 4 + j;
            if (n < N) {
                float v = acc[i][j] + bias[n];
                if (HAS_RES) v += Res[(size_t)m * N + n];
                C[(size_t)m * N + n] = v;
            }
        }
    }
}

// ---------------- K6: row softmax over 1000 logits (in-place on d_out) -------
__global__ __launch_bounds__(256) void softmax_kernel(float* __restrict__ out) {
    int b = blockIdx.x, tid = threadIdx.x;
    __shared__ float red[32];
    float v[4];
    float m = -INFINITY;
    #pragma unroll
    for (int u = 0; u < 4; u++) {
        int j = tid + 256 * u;
        v[u] = (j < NOUT) ? out[(size_t)b * NOUT + j] : -INFINITY;
        m = fmaxf(m, v[u]);
    }
    int lane = tid & 31, w = tid >> 5;
    #pragma unroll
    for (int o = 16; o > 0; o >>= 1) m = fmaxf(m, __shfl_xor_sync(0xffffffffu, m, o));
    if (lane == 0) red[w] = m;
    __syncthreads();
    if (tid < 8) {
        float x = red[tid];
        #pragma unroll
        for (int o = 4; o > 0; o >>= 1) x = fmaxf(x, __shfl_xor_sync(0xffu, x, o));
        if (tid == 0) red[0] = x;
    }
    __syncthreads();
    m = red[0];
    __syncthreads();
    float s = 0.f;
    #pragma unroll
    for (int u = 0; u < 4; u++) {
        int j = tid + 256 * u;
        if (j < NOUT) { v[u] = expf(v[u] - m); s += v[u]; }
    }
    s = block_reduce_sum256(s, red);
    float inv = 1.0f / s;
    #pragma unroll
    for (int u = 0; u < 4; u++) {
        int j = tid + 256 * u;
        if (j < NOUT) out[(size_t)b * NOUT + j] = v[u] * inv;
    }
}

// ---------------- launch ------------------------------------------------------
extern "C" void kernel_launch(void* const* d_in, const int* in_sizes, int n_in,
                              void* d_out, int out_size) {
    const float* x    = (const float*)d_in[0];
    const float* cls  = (const float*)d_in[1];
    const float* Wp   = (const float*)d_in[2];
    const float* ln1w = (const float*)d_in[3];
    const float* ln1b = (const float*)d_in[4];
    const float* Wq   = (const float*)d_in[5];
    const float* bq   = (const float*)d_in[6];
    const float* Wk   = (const float*)d_in[7];
    const float* bk   = (const float*)d_in[8];
    const float* Wv   = (const float*)d_in[9];
    const float* bv   = (const float*)d_in[10];
    const float* ln2w = (const float*)d_in[11];
    const float* ln2b = (const float*)d_in[12];
    const float* Wm   = (const float*)d_in[13];
    const float* bm   = (const float*)d_in[14];
    const float* Wh   = (const float*)d_in[15];
    const float* bh   = (const float*)d_in[16];
    float* out = (float*)d_out;

    float *p_n0 = nullptr, *p_tok0p = nullptr, *p_final = nullptr;
    cudaGetSymbolAddress((void**)&p_n0, g_n0);
    cudaGetSymbolAddress((void**)&p_tok0p, g_tok0p);
    cudaGetSymbolAddress((void**)&p_final, g_final);

    pe_kernel<<<SEQ, 256>>>();
    embed_ln1_kernel<<<dim3(SEQ, Bsz), 256>>>(x, cls, Wp, ln1w, ln1b);
    attn_kernel<<<dim3(NH, Bsz), 128>>>(Wq, bq, Wk, bk, Wv, bv);
    ln2_kernel<<<Bsz, 256>>>(ln2w, ln2b);
    gemm_nt_kernel<true><<<dim3(Dm / 64, Bsz / 64), 256>>>(
        p_n0, Wm, bm, p_tok0p, p_final, Bsz, Dm, Dm);
    gemm_nt_kernel<false><<<dim3((NOUT + 63) / 64, Bsz / 64), 256>>>(
        p_final, Wh, bh, nullptr, out, Bsz, NOUT, Dm);
    softmax_kernel<<<Bsz, 256>>>(out);
}

// round 2
// speedup vs baseline: 1.8136x; 1.8136x over previous
#include <cuda_runtime.h>
#include <math.h>

#define Bsz 1024
#define Dm 1024
#define NH 16
#define DHd 64
#define SEQ 50
#define NOUT 1000
#define LNEPS 1e-5f
#define NPAD 1025   // row stride for n[] in smem (bank-conflict padding)

// ---- smem layout (floats) ----
// n      : 50*1025              = 51250
// tok0   : 1024                   @ 51250
// tok0p  : 1024                   @ 52274
// scratch: 3*1024 (patches | qh,tvh,probs) @ 53298
// red    : 32                     @ 56370
#define OFF_TOK0   (SEQ * NPAD)
#define OFF_TOK0P  (OFF_TOK0 + Dm)
#define OFF_SCR    (OFF_TOK0P + Dm)
#define OFF_RED    (OFF_SCR + 3 * 1024)
#define SMEM_FLOATS (OFF_RED + 32)
#define SMEM_BYTES (SMEM_FLOATS * 4)

// ---------------- scratch globals (no allocation allowed) --------------------
__device__ float g_tok0p[Bsz * Dm];   // token-0 row after attention residual
__device__ float g_n0[Bsz * Dm];      // LN2 output
__device__ float g_final[Bsz * Dm];   // after MLP residual

// ============================================================================
// Fused front-end: patchify + embed + pos-emb + LN1 + algebraic attention
// (query row 0 only; K/V projections eliminated) + residual + LN2.
// One CTA per batch element, 1024 threads, everything in smem.
// ============================================================================
__global__ __launch_bounds__(1024) void fused_front(
    const float* __restrict__ x, const float* __restrict__ cls,
    const float* __restrict__ Wp,
    const float* __restrict__ ln1w, const float* __restrict__ ln1b,
    const float* __restrict__ Wq, const float* __restrict__ bq,
    const float* __restrict__ Wk, const float* __restrict__ bk,
    const float* __restrict__ Wv, const float* __restrict__ bv,
    const float* __restrict__ ln2w, const float* __restrict__ ln2b,
    float* __restrict__ out_tok0p, float* __restrict__ out_n0)
{
    extern __shared__ float sm[];
    float* n     = sm;
    float* tok0  = sm + OFF_TOK0;
    float* tok0p = sm + OFF_TOK0P;
    float* scr   = sm + OFF_SCR;        // patches (784f) / qh,tvh,probs
    float* red   = sm + OFF_RED;

    const int b   = blockIdx.x;
    const int tid = threadIdx.x;
    const int w    = tid >> 5;
    const int lane = tid & 31;

    // ---- Phase A: patchify x[b] (28x28) -> patches[49][16] -----------------
    {
        float* patches = scr;
        if (tid < 784) {
            int row = tid / 28, col = tid % 28;
            int pi = (row >> 2) * 7 + (col >> 2);
            int p  = (row & 3) * 4 + (col & 3);
            patches[pi * 16 + p] = x[b * 784 + tid];
        }
    }
    __syncthreads();

    // ---- Phase B: embed + pos-emb (computed inline), one d per thread ------
    {
        const float* patches = scr;
        int d = tid;
        float wr[16];
        #pragma unroll
        for (int p = 0; p < 16; p++) wr[p] = Wp[d * 16 + p];
        float freq = powf(10000.0f, -(float)(d & ~1) / (float)Dm);
        bool odd = (d & 1);

        float t0 = cls[d] + (odd ? 1.0f : 0.0f);   // s=0: sin(0)=0, cos(0)=1
        n[d] = t0;
        tok0[d] = t0;
        for (int s = 1; s < SEQ; s++) {
            const float* pp = &patches[(s - 1) * 16];
            float a = 0.f;
            #pragma unroll
            for (int p = 0; p < 16; p++) a += pp[p] * wr[p];
            float sa, ca;
            sincosf((float)s * freq, &sa, &ca);
            a += odd ? ca : sa;
            n[s * NPAD + d] = a;
        }
    }
    __syncthreads();

    // ---- Phase C: LN1 in place, one token per warp (two-pass) --------------
    for (int s = w; s < SEQ; s += 32) {
        float* row = &n[s * NPAD];
        float sum = 0.f;
        #pragma unroll
        for (int i = 0; i < 32; i++) sum += row[lane + 32 * i];
        #pragma unroll
        for (int o = 16; o > 0; o >>= 1) sum += __shfl_xor_sync(0xffffffffu, sum, o);
        float mu = sum * (1.0f / (float)Dm);
        float sq = 0.f;
        #pragma unroll
        for (int i = 0; i < 32; i++) { float dv = row[lane + 32 * i] - mu; sq += dv * dv; }
        #pragma unroll
        for (int o = 16; o > 0; o >>= 1) sq += __shfl_xor_sync(0xffffffffu, sq, o);
        float rstd = rsqrtf(sq * (1.0f / (float)Dm) + LNEPS);
        #pragma unroll
        for (int i = 0; i < 32; i++) {
            int d = lane + 32 * i;
            row[d] = (row[d] - mu) * rstd * ln1w[d] + ln1b[d];
        }
    }
    __syncthreads();

    // ---- Phase D: algebraic attention. 2 warps per head. -------------------
    // q0 = Wq x0 + bq ; sc_s = 32*((Wk^T q0).x_s + q0.bk) ; p = softmax(sc)
    // c = sum_s p_s x_s ; out = Wv c + bv ; tok0p = tok0 + out
    float* qh    = scr;               // [16][64]  q0, later reused as c
    float* tvh   = scr + 1024;        // [16][64]
    float* probs = scr + 2048;        // [16][64]  scores -> probabilities
    const int h    = w >> 1;
    const int half = w & 1;
    const int e    = half * 32 + lane;

    {   // q0
        const float* wrow = &Wq[(h * DHd + e) * DHd];
        const float* x0   = &n[h * DHd];
        float a = bq[h * DHd + e];
        #pragma unroll 16
        for (int d = 0; d < DHd; d++) a += wrow[d] * x0[d];
        qh[h * DHd + e] = a;
    }
    __syncthreads();

    {   // qbk (half==0 warp) and tv (both warps)
        if (half == 0) {
            float a = qh[h * DHd + lane] * bk[h * DHd + lane]
                    + qh[h * DHd + lane + 32] * bk[h * DHd + lane + 32];
            #pragma unroll
            for (int o = 16; o > 0; o >>= 1) a += __shfl_xor_sync(0xffffffffu, a, o);
            if (lane == 0) red[h] = a;
        }
        float a = 0.f;
        #pragma unroll 16
        for (int d = 0; d < DHd; d++) a += qh[h * DHd + d] * Wk[(h * DHd + d) * DHd + e];
        tvh[h * DHd + e] = a;
    }
    __syncthreads();

    {   // scores (s = e)
        int s = e;
        if (s < SEQ) {
            const float* xr = &n[s * NPAD + h * DHd];
            float a = red[h];
            #pragma unroll 16
            for (int d = 0; d < DHd; d++) a += tvh[h * DHd + d] * xr[d];
            probs[h * DHd + s] = a * 32.0f;   // * sqrt(D)
        }
    }
    __syncthreads();

    if (half == 0) {   // softmax over 50, one warp per head
        float v1 = probs[h * DHd + lane];
        float v2 = (lane + 32 < SEQ) ? probs[h * DHd + lane + 32] : -INFINITY;
        float m = fmaxf(v1, v2);
        #pragma unroll
        for (int o = 16; o > 0; o >>= 1) m = fmaxf(m, __shfl_xor_sync(0xffffffffu, m, o));
        float e1 = expf(v1 - m);
        float e2 = (lane + 32 < SEQ) ? expf(v2 - m) : 0.f;
        float ss = e1 + e2;
        #pragma unroll
        for (int o = 16; o > 0; o >>= 1) ss += __shfl_xor_sync(0xffffffffu, ss, o);
        float inv = 1.0f / ss;
        probs[h * DHd + lane] = e1 * inv;
        if (lane + 32 < SEQ) probs[h * DHd + lane + 32] = e2 * inv;
    }
    __syncthreads();

    {   // c = sum_s p_s x_s  (overwrite qh)
        int d = e;
        float a = 0.f;
        #pragma unroll 10
        for (int s = 0; s < SEQ; s++) a += probs[h * DHd + s] * n[s * NPAD + h * DHd + d];
        __syncwarp();
        qh[h * DHd + d] = a;
    }
    __syncthreads();

    {   // out = Wv c + bv ; residual
        const float* wrow = &Wv[(h * DHd + e) * DHd];
        float a = bv[h * DHd + e];
        #pragma unroll 16
        for (int d = 0; d < DHd; d++) a += wrow[d] * qh[h * DHd + d];
        tok0p[h * DHd + e] = tok0[h * DHd + e] + a;
    }
    __syncthreads();

    // ---- Phase E: LN2 over tok0p, write globals -----------------------------
    {
        float v = tok0p[tid];
        float s = v;
        #pragma unroll
        for (int o = 16; o > 0; o >>= 1) s += __shfl_xor_sync(0xffffffffu, s, o);
        if (lane == 0) red[w] = s;
        __syncthreads();
        if (tid < 32) {
            float x2 = red[tid];
            #pragma unroll
            for (int o = 16; o > 0; o >>= 1) x2 += __shfl_xor_sync(0xffffffffu, x2, o);
            if (tid == 0) red[0] = x2;
        }
        __syncthreads();
        float mu = red[0] * (1.0f / (float)Dm);
        __syncthreads();
        float dv = v - mu;
        float q = dv * dv;
        #pragma unroll
        for (int o = 16; o > 0; o >>= 1) q += __shfl_xor_sync(0xffffffffu, q, o);
        if (lane == 0) red[w] = q;
        __syncthreads();
        if (tid < 32) {
            float x2 = red[tid];
            #pragma unroll
            for (int o = 16; o > 0; o >>= 1) x2 += __shfl_xor_sync(0xffffffffu, x2, o);
            if (tid == 0) red[0] = x2;
        }
        __syncthreads();
        float rstd = rsqrtf(red[0] * (1.0f / (float)Dm) + LNEPS);
        out_tok0p[b * Dm + tid] = v;
        out_n0[b * Dm + tid]    = dv * rstd * ln2w[tid] + ln2b[tid];
    }
}

// ============================================================================
// Tiled fp32 GEMM: C = A * Bw^T + bias (+ Res).  64x64 tile, BK=16, 256 thr.
// Smem padded to 68 floats/row -> 16B-aligned LDS.128 in the inner loop.
// ============================================================================
template <bool HAS_RES>
__global__ __launch_bounds__(256) void gemm_nt_kernel(
    const float* __restrict__ A, const float* __restrict__ Bw,
    const float* __restrict__ bias, const float* __restrict__ Res,
    float* __restrict__ C, int M, int N, int K)
{
    __shared__ float As[16][68];
    __shared__ float Bs[16][68];
    int m0 = blockIdx.y * 64, n0 = blockIdx.x * 64;
    int tid = threadIdx.x;
    int lr = tid >> 2;       // 0..63 row within tile
    int lq = tid & 3;        // float4 index within 16-wide k slab
    int tx = tid & 15, ty = tid >> 4;
    float acc[4][4] = {};

    for (int k0 = 0; k0 < K; k0 += 16) {
        float4 av = *(const float4*)&A[(size_t)(m0 + lr) * K + k0 + lq * 4];
        float4 bv4 = make_float4(0.f, 0.f, 0.f, 0.f);
        int nr = n0 + lr;
        if (nr < N) bv4 = *(const float4*)&Bw[(size_t)nr * K + k0 + lq * 4];
        As[lq * 4 + 0][lr] = av.x;  As[lq * 4 + 1][lr] = av.y;
        As[lq * 4 + 2][lr] = av.z;  As[lq * 4 + 3][lr] = av.w;
        Bs[lq * 4 + 0][lr] = bv4.x; Bs[lq * 4 + 1][lr] = bv4.y;
        Bs[lq * 4 + 2][lr] = bv4.z; Bs[lq * 4 + 3][lr] = bv4.w;
        __syncthreads();
        #pragma unroll
        for (int k = 0; k < 16; k++) {
            float4 ar = *(const float4*)&As[k][ty * 4];
            float4 br = *(const float4*)&Bs[k][tx * 4];
            float arr[4] = {ar.x, ar.y, ar.z, ar.w};
            float brr[4] = {br.x, br.y, br.z, br.w};
            #pragma unroll
            for (int i = 0; i < 4; i++)
                #pragma unroll
                for (int j = 0; j < 4; j++) acc[i][j] += arr[i] * brr[j];
        }
        __syncthreads();
    }
    #pragma unroll
    for (int i = 0; i < 4; i++) {
        int m = m0 + ty * 4 + i;
        #pragma unroll
        for (int j = 0; j < 4; j++) {
            int nn = n0 + tx * 4 + j;
            if (nn < N) {
                float v = acc[i][j] + bias[nn];
                if (HAS_RES) v += Res[(size_t)m * N + nn];
                C[(size_t)m * N + nn] = v;
            }
        }
    }
}

// ============================================================================
// Row softmax over 1000 logits (in-place on d_out)
// ============================================================================
__global__ __launch_bounds__(256) void softmax_kernel(float* __restrict__ out) {
    int b = blockIdx.x, tid = threadIdx.x;
    __shared__ float red[32];
    int lane = tid & 31, w = tid >> 5;
    float v[4];
    float m = -INFINITY;
    #pragma unroll
    for (int u = 0; u < 4; u++) {
        int j = tid + 256 * u;
        v[u] = (j < NOUT) ? out[(size_t)b * NOUT + j] : -INFINITY;
        m = fmaxf(m, v[u]);
    }
    #pragma unroll
    for (int o = 16; o > 0; o >>= 1) m = fmaxf(m, __shfl_xor_sync(0xffffffffu, m, o));
    if (lane == 0) red[w] = m;
    __syncthreads();
    if (tid < 8) {
        float x2 = red[tid];
        #pragma unroll
        for (int o = 4; o > 0; o >>= 1) x2 = fmaxf(x2, __shfl_xor_sync(0xffu, x2, o));
        if (tid == 0) red[0] = x2;
    }
    __syncthreads();
    m = red[0];
    __syncthreads();
    float s = 0.f;
    #pragma unroll
    for (int u = 0; u < 4; u++) {
        int j = tid + 256 * u;
        if (j < NOUT) { v[u] = expf(v[u] - m); s += v[u]; }
    }
    #pragma unroll
    for (int o = 16; o > 0; o >>= 1) s += __shfl_xor_sync(0xffffffffu, s, o);
    if (lane == 0) red[w] = s;
    __syncthreads();
    if (tid < 8) {
        float x2 = red[tid];
        #pragma unroll
        for (int o = 4; o > 0; o >>= 1) x2 += __shfl_xor_sync(0xffu, x2, o);
        if (tid == 0) red[0] = x2;
    }
    __syncthreads();
    float inv = 1.0f / red[0];
    #pragma unroll
    for (int u = 0; u < 4; u++) {
        int j = tid + 256 * u;
        if (j < NOUT) out[(size_t)b * NOUT + j] = v[u] * inv;
    }
}

// ---------------- launch ------------------------------------------------------
extern "C" void kernel_launch(void* const* d_in, const int* in_sizes, int n_in,
                              void* d_out, int out_size) {
    const float* x    = (const float*)d_in[0];
    const float* cls  = (const float*)d_in[1];
    const float* Wp   = (const float*)d_in[2];
    const float* ln1w = (const float*)d_in[3];
    const float* ln1b = (const float*)d_in[4];
    const float* Wq   = (const float*)d_in[5];
    const float* bq   = (const float*)d_in[6];
    const float* Wk   = (const float*)d_in[7];
    const float* bk   = (const float*)d_in[8];
    const float* Wv   = (const float*)d_in[9];
    const float* bv   = (const float*)d_in[10];
    const float* ln2w = (const float*)d_in[11];
    const float* ln2b = (const float*)d_in[12];
    const float* Wm   = (const float*)d_in[13];
    const float* bm   = (const float*)d_in[14];
    const float* Wh   = (const float*)d_in[15];
    const float* bh   = (const float*)d_in[16];
    float* out = (float*)d_out;

    float *p_n0 = nullptr, *p_tok0p = nullptr, *p_final = nullptr;
    cudaGetSymbolAddress((void**)&p_n0, g_n0);
    cudaGetSymbolAddress((void**)&p_tok0p, g_tok0p);
    cudaGetSymbolAddress((void**)&p_final, g_final);

    static bool attr_set = false;
    if (!attr_set) {
        cudaFuncSetAttribute(fused_front,
                             cudaFuncAttributeMaxDynamicSharedMemorySize, SMEM_BYTES);
        attr_set = true;
    }

    fused_front<<<Bsz, 1024, SMEM_BYTES>>>(
        x, cls, Wp, ln1w, ln1b, Wq, bq, Wk, bk, Wv, bv, ln2w, ln2b,
        p_tok0p, p_n0);
    gemm_nt_kernel<true><<<dim3(Dm / 64, Bsz / 64), 256>>>(
        p_n0, Wm, bm, p_tok0p, p_final, Bsz, Dm, Dm);
    gemm_nt_kernel<false><<<dim3((NOUT + 63) / 64, Bsz / 64), 256>>>(
        p_final, Wh, bh, nullptr, out, Bsz, NOUT, Dm);
    softmax_kernel<<<Bsz, 256>>>(out);
}

// round 3
// speedup vs baseline: 4.2483x; 2.3424x over previous
#include <cuda_runtime.h>
#include <math.h>

#define Bsz 1024
#define Dm 1024
#define NH 16
#define DHd 64
#define SEQ 50
#define NOUT 1000
#define LNEPS 1e-5f

// ---------------- scratch globals ------------------------------------------
__device__ float g_pe[SEQ * Dm];      // pos-emb table
__device__ float g_hh[SEQ * 16];      // Wp^T pe_s  (per token, 16)
__device__ float g_pesum[SEQ];        // sum_d pe[s,d]
__device__ float g_pesq[SEQ];         // sum_d pe[s,d]^2
__device__ float g_G[256];            // Gram = Wp^T Wp (16x16)
__device__ float g_cs[16];            // column sums of Wp
__device__ float g_x0[Dm];            // LN1(cls+pe0)
__device__ float g_tok0[Dm];          // cls+pe0
__device__ float g_vproj[NH * 16];    // Wp^T u_h
__device__ float g_pep[NH * SEQ];     // pe^T u_h
__device__ float g_su[NH];            // sum u_h
__device__ float g_gam[NH];           // tv.ln1b + q0.bk
__device__ float g_sc0[NH];           // score for s=0
__device__ float g_tok0p[Bsz * Dm];
__device__ float g_n0[Bsz * Dm];
__device__ float g_final[Bsz * Dm];

// ---------------- reduce helpers --------------------------------------------
__device__ __forceinline__ float bred256(float v, float* red) {
    int tid = threadIdx.x, lane = tid & 31, w = tid >> 5;
    #pragma unroll
    for (int o = 16; o > 0; o >>= 1) v += __shfl_xor_sync(0xffffffffu, v, o);
    if (lane == 0) red[w] = v;
    __syncthreads();
    float r = 0.f;
    if (tid < 8) {
        r = red[tid];
        #pragma unroll
        for (int o = 4; o > 0; o >>= 1) r += __shfl_xor_sync(0xffu, r, o);
        if (tid == 0) red[0] = r;
    }
    __syncthreads();
    r = red[0];
    __syncthreads();
    return r;
}

__device__ __forceinline__ float bred_generic(float v, float* red, int nwarps) {
    int tid = threadIdx.x, lane = tid & 31, w = tid >> 5;
    #pragma unroll
    for (int o = 16; o > 0; o >>= 1) v += __shfl_xor_sync(0xffffffffu, v, o);
    if (lane == 0) red[w] = v;
    __syncthreads();
    float r = 0.f;
    if (tid < 32) {
        r = (tid < nwarps) ? red[tid] : 0.f;
        #pragma unroll
        for (int o = 16; o > 0; o >>= 1) r += __shfl_xor_sync(0xffffffffu, r, o);
        if (tid == 0) red[0] = r;
    }
    __syncthreads();
    r = red[0];
    __syncthreads();
    return r;
}

// ---------------- K0: pe table + per-token pe stats + Wp^T pe ----------------
__global__ __launch_bounds__(256) void k_pe(const float* __restrict__ Wp) {
    int s = blockIdx.x, tid = threadIdx.x;
    __shared__ float red[8];
    float v[4];
    #pragma unroll
    for (int u = 0; u < 4; u++) {
        int d = tid + 256 * u;
        float freq = powf(10000.f, -(float)(d & ~1) / (float)Dm);
        float sa, ca;
        sincosf((float)s * freq, &sa, &ca);
        float p = (d & 1) ? ca : sa;
        g_pe[s * Dm + d] = p;
        v[u] = p;
    }
    float ps = bred256(v[0] + v[1] + v[2] + v[3], red);
    float pq = bred256(v[0]*v[0] + v[1]*v[1] + v[2]*v[2] + v[3]*v[3], red);
    if (tid == 0) { g_pesum[s] = ps; g_pesq[s] = pq; }
    for (int p = 0; p < 16; p++) {
        float a = 0.f;
        #pragma unroll
        for (int u = 0; u < 4; u++) a += Wp[(tid + 256 * u) * 16 + p] * v[u];
        float r = bred256(a, red);
        if (tid == 0) g_hh[s * 16 + p] = r;
    }
}

// ---------------- K0b: Gram matrix + column sums of Wp ----------------------
__global__ __launch_bounds__(256) void k_gram(const float* __restrict__ Wp) {
    int p = blockIdx.x, tid = threadIdx.x;
    __shared__ float red[8];
    float acc[16];
    #pragma unroll
    for (int q = 0; q < 16; q++) acc[q] = 0.f;
    float cs = 0.f;
    for (int d = tid; d < Dm; d += 256) {
        float wdp = Wp[d * 16 + p];
        cs += wdp;
        #pragma unroll
        for (int q = 0; q < 16; q++) acc[q] += wdp * Wp[d * 16 + q];
    }
    for (int q = 0; q < 16; q++) {
        float r = bred256(acc[q], red);
        if (tid == 0) g_G[p * 16 + q] = r;
    }
    float r = bred256(cs, red);
    if (tid == 0) g_cs[p] = r;
}

// ---------------- K1a: token0 + LN1(token0) ---------------------------------
__global__ __launch_bounds__(1024) void k_tok0(
    const float* __restrict__ cls, const float* __restrict__ ln1w,
    const float* __restrict__ ln1b)
{
    int tid = threadIdx.x;
    __shared__ float red[32];
    float v = cls[tid] + g_pe[tid];
    g_tok0[tid] = v;
    float mu = bred_generic(v, red, 32) * (1.0f / (float)Dm);
    float dv = v - mu;
    float var = bred_generic(dv * dv, red, 32) * (1.0f / (float)Dm);
    float rstd = rsqrtf(var + LNEPS);
    g_x0[tid] = dv * rstd * ln1w[tid] + ln1b[tid];
}

// ---------------- K1b: per-head precompute (q0, tv, u, projections) ---------
__global__ __launch_bounds__(64) void k_head(
    const float* __restrict__ Wq, const float* __restrict__ bq,
    const float* __restrict__ Wk, const float* __restrict__ bk,
    const float* __restrict__ ln1w, const float* __restrict__ ln1b,
    const float* __restrict__ Wp)
{
    int h = blockIdx.x, tid = threadIdx.x;
    __shared__ float x0s[64], q0s[64], tvs[64], us[64];
    __shared__ float red[2];
    x0s[tid] = g_x0[h * DHd + tid];
    __syncthreads();

    {   // q0
        float a = bq[h * DHd + tid];
        const float* wr = &Wq[(h * DHd + tid) * DHd];
        #pragma unroll 16
        for (int d = 0; d < DHd; d++) a += wr[d] * x0s[d];
        q0s[tid] = a;
    }
    __syncthreads();

    float qbk = bred_generic(q0s[tid] * bk[h * DHd + tid], red, 2);

    {   // tv = Wk^T q0, u = tv*ln1w
        float a = 0.f;
        #pragma unroll 16
        for (int d = 0; d < DHd; d++) a += q0s[d] * Wk[(h * DHd + d) * DHd + tid];
        tvs[tid] = a;
        us[tid] = a * ln1w[h * DHd + tid];
    }
    __syncthreads();

    float su = bred_generic(us[tid], red, 2);
    float gp = bred_generic(tvs[tid] * ln1b[h * DHd + tid], red, 2);
    float s0 = bred_generic(tvs[tid] * x0s[tid], red, 2);
    if (tid == 0) {
        g_su[h] = su;
        g_gam[h] = gp + qbk;
        g_sc0[h] = 32.0f * (s0 + qbk);
    }
    if (tid < 16) {
        float a = 0.f;
        #pragma unroll 16
        for (int d = 0; d < DHd; d++) a += us[d] * Wp[(h * DHd + d) * 16 + tid];
        g_vproj[h * 16 + tid] = a;
    }
    if (tid < SEQ) {
        float a = 0.f;
        #pragma unroll 16
        for (int d = 0; d < DHd; d++) a += us[d] * g_pe[tid * Dm + h * DHd + d];
        g_pep[h * SEQ + tid] = a;
    }
}

// ---------------- K2: main per-batch kernel ----------------------------------
// grid=Bsz, 512 threads. Attention on query row 0 without materializing tokens.
__global__ __launch_bounds__(512) void k_main(
    const float* __restrict__ x,
    const float* __restrict__ ln1w, const float* __restrict__ ln1b,
    const float* __restrict__ Wv, const float* __restrict__ bv,
    const float* __restrict__ Wp,
    const float* __restrict__ ln2w, const float* __restrict__ ln2b)
{
    __shared__ float pa[49 * 16];
    __shared__ float mu[SEQ], rsd[SEQ];
    __shared__ float sc[NH * 52];
    __shared__ float rr[NH * 52];
    __shared__ float qt[NH * 16];
    __shared__ float cc[NH * DHd];
    __shared__ float t0p[Dm];
    __shared__ float p0s[NH], mbars[NH];
    __shared__ float red[16];

    const int b = blockIdx.x, tid = threadIdx.x;
    const int w = tid >> 5, lane = tid & 31;

    // Phase 1: patchify
    if (tid == 0) { mu[0] = 0.f; rsd[0] = 0.f; }
    for (int idx = tid; idx < 784; idx += 512) {
        int row = idx / 28, col = idx % 28;
        int pi = (row >> 2) * 7 + (col >> 2);
        int pp = (row & 3) * 4 + (col & 3);
        pa[pi * 16 + pp] = x[b * 784 + idx];
    }
    __syncthreads();

    // Phase 2: per-token LN stats from the quadratic form (warp per token)
    for (int sidx = w; sidx < 49; sidx += 16) {
        int s = sidx + 1;
        float e2p = 0.f, mup = 0.f;
        if (lane < 16) {
            int p = lane;
            float pap = pa[sidx * 16 + p];
            float y = 0.f;
            #pragma unroll
            for (int q = 0; q < 16; q++) y += g_G[p * 16 + q] * pa[sidx * 16 + q];
            e2p = pap * (y + 2.0f * g_hh[s * 16 + p]);
            mup = pap * g_cs[p];
        }
        #pragma unroll
        for (int o = 8; o > 0; o >>= 1) {
            e2p += __shfl_down_sync(0xffffffffu, e2p, o);
            mup += __shfl_down_sync(0xffffffffu, mup, o);
        }
        if (lane == 0) {
            float m = (mup + g_pesum[s]) * (1.0f / (float)Dm);
            float e2 = e2p + g_pesq[s];
            float var = e2 * (1.0f / (float)Dm) - m * m;
            mu[s] = m;
            rsd[s] = rsqrtf(var + LNEPS);
        }
    }
    __syncthreads();

    // Phase 3: scores for all (h, s)
    for (int t = tid; t < NH * SEQ; t += 512) {
        int h = t / SEQ, s = t % SEQ;
        float v;
        if (s == 0) {
            v = g_sc0[h];
        } else {
            float g = g_pep[h * SEQ + s];
            const float* pr = &pa[(s - 1) * 16];
            const float* vp = &g_vproj[h * 16];
            #pragma unroll
            for (int p = 0; p < 16; p++) g += pr[p] * vp[p];
            v = 32.0f * (rsd[s] * (g - mu[s] * g_su[h]) + g_gam[h]);
        }
        sc[h * 52 + s] = v;
    }
    __syncthreads();

    // Phase 4: softmax per head (warp per head) -> r_s = p_s*rstd_s, m-bar, p0
    {
        int h = w;
        float v1 = sc[h * 52 + lane];
        float v2 = (lane + 32 < SEQ) ? sc[h * 52 + lane + 32] : -INFINITY;
        float m = fmaxf(v1, v2);
        #pragma unroll
        for (int o = 16; o > 0; o >>= 1) m = fmaxf(m, __shfl_xor_sync(0xffffffffu, m, o));
        float e1 = expf(v1 - m);
        float e2 = (lane + 32 < SEQ) ? expf(v2 - m) : 0.f;
        float ss = e1 + e2;
        #pragma unroll
        for (int o = 16; o > 0; o >>= 1) ss += __shfl_xor_sync(0xffffffffu, ss, o);
        float inv = 1.0f / ss;
        float p1 = e1 * inv, p2 = e2 * inv;
        float r1 = (lane == 0) ? 0.f : p1 * rsd[lane];
        float r2 = (lane + 32 < SEQ) ? p2 * rsd[lane + 32] : 0.f;
        rr[h * 52 + lane] = r1;
        if (lane + 32 < SEQ) rr[h * 52 + lane + 32] = r2;
        float mb = r1 * mu[lane] + ((lane + 32 < SEQ) ? r2 * mu[lane + 32] : 0.f);
        #pragma unroll
        for (int o = 16; o > 0; o >>= 1) mb += __shfl_xor_sync(0xffffffffu, mb, o);
        if (lane == 0) { mbars[h] = mb; p0s[h] = p1; }
    }
    __syncthreads();

    // Phase 5: weighted patch sums q~_p (warp per head)
    {
        int h = w;
        if (lane < 16) {
            int p = lane;
            float a = 0.f;
            #pragma unroll 7
            for (int sidx = 0; sidx < 49; sidx++)
                a += rr[h * 52 + sidx + 1] * pa[sidx * 16 + p];
            qt[h * 16 + p] = a;
        }
    }
    __syncthreads();

    // Phase 6: context vector c (warp per head)
    {
        int h = w;
        float p0 = p0s[h], mb = mbars[h];
        #pragma unroll
        for (int i = 0; i < 2; i++) {
            int d = lane + 32 * i, gd = h * DHd + d;
            float t1 = 0.f;
            const float* wr = &Wp[gd * 16];
            #pragma unroll
            for (int p = 0; p < 16; p++) t1 += qt[h * 16 + p] * wr[p];
            float t2 = 0.f;
            #pragma unroll 7
            for (int s = 1; s < SEQ; s++) t2 += rr[h * 52 + s] * g_pe[s * Dm + gd];
            cc[h * DHd + d] = ln1w[gd] * (t1 + t2 - mb)
                            + (1.0f - p0) * ln1b[gd] + p0 * g_x0[gd];
        }
    }
    __syncthreads();

    // Phase 7: out = Wv c + bv ; residual with tok0
    {
        int h = w;
        #pragma unroll
        for (int i = 0; i < 2; i++) {
            int e = lane + 32 * i, ge = h * DHd + e;
            float a = bv[ge];
            const float* wr = &Wv[ge * DHd];
            #pragma unroll 16
            for (int d = 0; d < DHd; d++) a += wr[d] * cc[h * DHd + d];
            t0p[ge] = g_tok0[ge] + a;
        }
    }
    __syncthreads();

    // Phase 8: LN2, write outputs
    {
        float v0 = t0p[tid], v1 = t0p[tid + 512];
        float s = bred_generic(v0 + v1, red, 16);
        float m = s * (1.0f / (float)Dm);
        float d0 = v0 - m, d1 = v1 - m;
        float q = bred_generic(d0 * d0 + d1 * d1, red, 16);
        float rstd = rsqrtf(q * (1.0f / (float)Dm) + LNEPS);
        g_tok0p[b * Dm + tid] = v0;
        g_tok0p[b * Dm + tid + 512] = v1;
        g_n0[b * Dm + tid] = d0 * rstd * ln2w[tid] + ln2b[tid];
        g_n0[b * Dm + tid + 512] = d1 * rstd * ln2w[tid + 512] + ln2b[tid + 512];
    }
}

// ---------------- GEMM: C = A * Bw^T + bias (+ Res) --------------------------
template <bool HAS_RES>
__global__ __launch_bounds__(256) void gemm_nt_kernel(
    const float* __restrict__ A, const float* __restrict__ Bw,
    const float* __restrict__ bias, const float* __restrict__ Res,
    float* __restrict__ C, int M, int N, int K)
{
    __shared__ float As[16][68];
    __shared__ float Bs[16][68];
    int m0 = blockIdx.y * 64, n0 = blockIdx.x * 64;
    int tid = threadIdx.x;
    int lr = tid >> 2;
    int lq = tid & 3;
    int tx = tid & 15, ty = tid >> 4;
    float acc[4][4] = {};

    for (int k0 = 0; k0 < K; k0 += 16) {
        float4 av = *(const float4*)&A[(size_t)(m0 + lr) * K + k0 + lq * 4];
        float4 bv4 = make_float4(0.f, 0.f, 0.f, 0.f);
        int nr = n0 + lr;
        if (nr < N) bv4 = *(const float4*)&Bw[(size_t)nr * K + k0 + lq * 4];
        As[lq * 4 + 0][lr] = av.x;  As[lq * 4 + 1][lr] = av.y;
        As[lq * 4 + 2][lr] = av.z;  As[lq * 4 + 3][lr] = av.w;
        Bs[lq * 4 + 0][lr] = bv4.x; Bs[lq * 4 + 1][lr] = bv4.y;
        Bs[lq * 4 + 2][lr] = bv4.z; Bs[lq * 4 + 3][lr] = bv4.w;
        __syncthreads();
        #pragma unroll
        for (int k = 0; k < 16; k++) {
            float4 ar = *(const float4*)&As[k][ty * 4];
            float4 br = *(const float4*)&Bs[k][tx * 4];
            float arr[4] = {ar.x, ar.y, ar.z, ar.w};
            float brr[4] = {br.x, br.y, br.z, br.w};
            #pragma unroll
            for (int i = 0; i < 4; i++)
                #pragma unroll
                for (int j = 0; j < 4; j++) acc[i][j] += arr[i] * brr[j];
        }
        __syncthreads();
    }
    #pragma unroll
    for (int i = 0; i < 4; i++) {
        int m = m0 + ty * 4 + i;
        #pragma unroll
        for (int j = 0; j < 4; j++) {
            int nn = n0 + tx * 4 + j;
            if (nn < N) {
                float v = acc[i][j] + bias[nn];
                if (HAS_RES) v += Res[(size_t)m * N + nn];
                C[(size_t)m * N + nn] = v;
            }
        }
    }
}

// ---------------- softmax over 1000 logits -----------------------------------
__global__ __launch_bounds__(256) void softmax_kernel(float* __restrict__ out) {
    int b = blockIdx.x, tid = threadIdx.x;
    __shared__ float red[32];
    int lane = tid & 31, w = tid >> 5;
    float v[4];
    float m = -INFINITY;
    #pragma unroll
    for (int u = 0; u < 4; u++) {
        int j = tid + 256 * u;
        v[u] = (j < NOUT) ? out[(size_t)b * NOUT + j] : -INFINITY;
        m = fmaxf(m, v[u]);
    }
    #pragma unroll
    for (int o = 16; o > 0; o >>= 1) m = fmaxf(m, __shfl_xor_sync(0xffffffffu, m, o));
    if (lane == 0) red[w] = m;
    __syncthreads();
    if (tid < 8) {
        float x2 = red[tid];
        #pragma unroll
        for (int o = 4; o > 0; o >>= 1) x2 = fmaxf(x2, __shfl_xor_sync(0xffu, x2, o));
        if (tid == 0) red[0] = x2;
    }
    __syncthreads();
    m = red[0];
    __syncthreads();
    float s = 0.f;
    #pragma unroll
    for (int u = 0; u < 4; u++) {
        int j = tid + 256 * u;
        if (j < NOUT) { v[u] = expf(v[u] - m); s += v[u]; }
    }
    #pragma unroll
    for (int o = 16; o > 0; o >>= 1) s += __shfl_xor_sync(0xffffffffu, s, o);
    if (lane == 0) red[w] = s;
    __syncthreads();
    if (tid < 8) {
        float x2 = red[tid];
        #pragma unroll
        for (int o = 4; o > 0; o >>= 1) x2 += __shfl_xor_sync(0xffu, x2, o);
        if (tid == 0) red[0] = x2;
    }
    __syncthreads();
    float inv = 1.0f / red[0];
    #pragma unroll
    for (int u = 0; u < 4; u++) {
        int j = tid + 256 * u;
        if (j < NOUT) out[(size_t)b * NOUT + j] = v[u] * inv;
    }
}

// ---------------- launch ------------------------------------------------------
extern "C" void kernel_launch(void* const* d_in, const int* in_sizes, int n_in,
                              void* d_out, int out_size) {
    const float* x    = (const float*)d_in[0];
    const float* cls  = (const float*)d_in[1];
    const float* Wp   = (const float*)d_in[2];
    const float* ln1w = (const float*)d_in[3];
    const float* ln1b = (const float*)d_in[4];
    const float* Wq   = (const float*)d_in[5];
    const float* bq   = (const float*)d_in[6];
    const float* Wk   = (const float*)d_in[7];
    const float* bk   = (const float*)d_in[8];
    const float* Wv   = (const float*)d_in[9];
    const float* bv   = (const float*)d_in[10];
    const float* ln2w = (const float*)d_in[11];
    const float* ln2b = (const float*)d_in[12];
    const float* Wm   = (const float*)d_in[13];
    const float* bm   = (const float*)d_in[14];
    const float* Wh   = (const float*)d_in[15];
    const float* bh   = (const float*)d_in[16];
    float* out = (float*)d_out;

    float *p_n0 = nullptr, *p_tok0p = nullptr, *p_final = nullptr;
    cudaGetSymbolAddress((void**)&p_n0, g_n0);
    cudaGetSymbolAddress((void**)&p_tok0p, g_tok0p);
    cudaGetSymbolAddress((void**)&p_final, g_final);

    k_pe<<<SEQ, 256>>>(Wp);
    k_gram<<<16, 256>>>(Wp);
    k_tok0<<<1, 1024>>>(cls, ln1w, ln1b);
    k_head<<<NH, 64>>>(Wq, bq, Wk, bk, ln1w, ln1b, Wp);
    k_main<<<Bsz, 512>>>(x, ln1w, ln1b, Wv, bv, Wp, ln2w, ln2b);
    gemm_nt_kernel<true><<<dim3(Dm / 64, Bsz / 64), 256>>>(
        p_n0, Wm, bm, p_tok0p, p_final, Bsz, Dm, Dm);
    gemm_nt_kernel<false><<<dim3((NOUT + 63) / 64, Bsz / 64), 256>>>(
        p_final, Wh, bh, nullptr, out, Bsz, NOUT, Dm);
    softmax_kernel<<<Bsz, 256>>>(out);
}

// round 4
// speedup vs baseline: 7.4036x; 1.7427x over previous
#include <cuda_runtime.h>
#include <math.h>

#define Bsz 1024
#define Dm 1024
#define NH 16
#define DHd 64
#define SEQ 50
#define NOUT 1000
#define LNEPS 1e-5f
#define BT 4                      // batch elements per k_main block

// ---------------- scratch globals ------------------------------------------
__device__ float g_pe[SEQ * Dm];      // pos-emb table
__device__ float g_hh[SEQ * 16];      // Wp^T pe_s
__device__ float g_pesum[SEQ];
__device__ float g_pesq[SEQ];
__device__ float g_G[256];            // Wp^T Wp
__device__ float g_cs[16];            // col sums of Wp
__device__ float g_x0[Dm];            // LN1(cls+pe0)
__device__ float g_tok0[Dm];          // cls+pe0
__device__ float g_vproj[NH * 16];    // Wp^T u_h
__device__ float g_pep[NH * SEQ];     // pe^T u_h
__device__ float g_su[NH];
__device__ float g_gam[NH];
__device__ float g_sc0[NH];
__device__ float g_tok0p[Bsz * Dm];
__device__ float g_n0[Bsz * Dm];
__device__ float g_final[Bsz * Dm];

// ---------------- reduce helpers --------------------------------------------
__device__ __forceinline__ float bred256(float v, float* red) {
    int tid = threadIdx.x, lane = tid & 31, w = tid >> 5;
    #pragma unroll
    for (int o = 16; o > 0; o >>= 1) v += __shfl_xor_sync(0xffffffffu, v, o);
    if (lane == 0) red[w] = v;
    __syncthreads();
    float r = 0.f;
    if (tid < 8) {
        r = red[tid];
        #pragma unroll
        for (int o = 4; o > 0; o >>= 1) r += __shfl_xor_sync(0xffu, r, o);
        if (tid == 0) red[0] = r;
    }
    __syncthreads();
    r = red[0];
    __syncthreads();
    return r;
}

__device__ __forceinline__ float bred_generic(float v, float* red, int nwarps) {
    int tid = threadIdx.x, lane = tid & 31, w = tid >> 5;
    #pragma unroll
    for (int o = 16; o > 0; o >>= 1) v += __shfl_xor_sync(0xffffffffu, v, o);
    if (lane == 0) red[w] = v;
    __syncthreads();
    float r = 0.f;
    if (tid < 32) {
        r = (tid < nwarps) ? red[tid] : 0.f;
        #pragma unroll
        for (int o = 16; o > 0; o >>= 1) r += __shfl_xor_sync(0xffffffffu, r, o);
        if (tid == 0) red[0] = r;
    }
    __syncthreads();
    r = red[0];
    __syncthreads();
    return r;
}

// ============================================================================
// K_PRE: ALL batch-independent precompute in one kernel, 83 independent blocks
//   blocks 0..49  : pe table row s + pe stats + Wp^T pe_s
//   blocks 50..65 : Gram column p
//   block  66     : tok0 + LN1(tok0)
//   blocks 67..82 : per-head q0/tv/u precompute (x0 + pe recomputed inline)
// ============================================================================
__global__ __launch_bounds__(256) void k_pre(
    const float* __restrict__ Wp, const float* __restrict__ cls,
    const float* __restrict__ ln1w, const float* __restrict__ ln1b,
    const float* __restrict__ Wq, const float* __restrict__ bq,
    const float* __restrict__ Wk, const float* __restrict__ bk)
{
    __shared__ float red[8];
    __shared__ float x0s[64], q0s[64], tvs[64], us[64], arr[64], freqs[64];
    __shared__ float hres[4];
    const int bid = blockIdx.x, tid = threadIdx.x;

    if (bid < 50) {                       // ---- pe row s ----
        int s = bid;
        float v[4];
        #pragma unroll
        for (int u = 0; u < 4; u++) {
            int d = tid + 256 * u;
            float freq = powf(10000.f, -(float)(d & ~1) / (float)Dm);
            float sa, ca;
            sincosf((float)s * freq, &sa, &ca);
            float p = (d & 1) ? ca : sa;
            g_pe[s * Dm + d] = p;
            v[u] = p;
        }
        float ps = bred256(v[0] + v[1] + v[2] + v[3], red);
        float pq = bred256(v[0]*v[0] + v[1]*v[1] + v[2]*v[2] + v[3]*v[3], red);
        if (tid == 0) { g_pesum[s] = ps; g_pesq[s] = pq; }
        for (int p = 0; p < 16; p++) {
            float a = 0.f;
            #pragma unroll
            for (int u = 0; u < 4; u++) a += Wp[(tid + 256 * u) * 16 + p] * v[u];
            float r = bred256(a, red);
            if (tid == 0) g_hh[s * 16 + p] = r;
        }
    } else if (bid < 66) {                // ---- Gram column p ----
        int p = bid - 50;
        float acc[16];
        #pragma unroll
        for (int q = 0; q < 16; q++) acc[q] = 0.f;
        float cs = 0.f;
        for (int d = tid; d < Dm; d += 256) {
            float wdp = Wp[d * 16 + p];
            cs += wdp;
            #pragma unroll
            for (int q = 0; q < 16; q++) acc[q] += wdp * Wp[d * 16 + q];
        }
        for (int q = 0; q < 16; q++) {
            float r = bred256(acc[q], red);
            if (tid == 0) g_G[p * 16 + q] = r;
        }
        float r = bred256(cs, red);
        if (tid == 0) g_cs[p] = r;
    } else if (bid == 66) {               // ---- tok0 + LN1(tok0) ----
        float v[4];
        float s1 = 0.f;
        #pragma unroll
        for (int u = 0; u < 4; u++) {
            int d = tid + 256 * u;
            float pe0 = (d & 1) ? 1.f : 0.f;
            v[u] = cls[d] + pe0;
            g_tok0[d] = v[u];
            s1 += v[u];
        }
        float mu = bred256(s1, red) * (1.0f / (float)Dm);
        float s2 = 0.f;
        #pragma unroll
        for (int u = 0; u < 4; u++) { float dv = v[u] - mu; s2 += dv * dv; }
        float var = bred256(s2, red) * (1.0f / (float)Dm);
        float rstd = rsqrtf(var + LNEPS);
        #pragma unroll
        for (int u = 0; u < 4; u++) {
            int d = tid + 256 * u;
            g_x0[d] = (v[u] - mu) * rstd * ln1w[d] + ln1b[d];
        }
    } else {                              // ---- per-head precompute ----
        int h = bid - 67;
        // full-row LN stats of cls+pe0 (two-pass)
        float s1 = 0.f;
        #pragma unroll
        for (int u = 0; u < 4; u++) {
            int d = tid + 256 * u;
            s1 += cls[d] + ((d & 1) ? 1.f : 0.f);
        }
        float mu = bred256(s1, red) * (1.0f / (float)Dm);
        float s2 = 0.f;
        #pragma unroll
        for (int u = 0; u < 4; u++) {
            int d = tid + 256 * u;
            float dv = cls[d] + ((d & 1) ? 1.f : 0.f) - mu;
            s2 += dv * dv;
        }
        float var = bred256(s2, red) * (1.0f / (float)Dm);
        float rstd = rsqrtf(var + LNEPS);

        if (tid < 64) {
            int gd = h * DHd + tid;
            float val = cls[gd] + ((gd & 1) ? 1.f : 0.f);
            x0s[tid] = (val - mu) * rstd * ln1w[gd] + ln1b[gd];
            freqs[tid] = powf(10000.f, -(float)(gd & ~1) / (float)Dm);
        }
        __syncthreads();

        if (tid < 64) {   // q0
            float a = bq[h * DHd + tid];
            const float* wr = &Wq[(h * DHd + tid) * DHd];
            #pragma unroll 16
            for (int d = 0; d < DHd; d++) a += wr[d] * x0s[d];
            q0s[tid] = a;
        }
        __syncthreads();

        // qbk
        if (tid < 64) arr[tid] = q0s[tid] * bk[h * DHd + tid];
        __syncthreads();
        if (tid < 32) {
            float a = arr[tid] + arr[tid + 32];
            #pragma unroll
            for (int o = 16; o > 0; o >>= 1) a += __shfl_down_sync(0xffffffffu, a, o);
            if (tid == 0) hres[0] = a;
        }
        __syncthreads();

        if (tid < 64) {   // tv = Wk^T q0, u = tv*ln1w
            float a = 0.f;
            #pragma unroll 16
            for (int d = 0; d < DHd; d++) a += q0s[d] * Wk[(h * DHd + d) * DHd + tid];
            tvs[tid] = a;
            us[tid] = a * ln1w[h * DHd + tid];
        }
        __syncthreads();

        // su, gp, s0
        if (tid < 64) arr[tid] = us[tid];
        __syncthreads();
        if (tid < 32) {
            float a = arr[tid] + arr[tid + 32];
            #pragma unroll
            for (int o = 16; o > 0; o >>= 1) a += __shfl_down_sync(0xffffffffu, a, o);
            if (tid == 0) hres[1] = a;
        }
        __syncthreads();
        if (tid < 64) arr[tid] = tvs[tid] * ln1b[h * DHd + tid];
        __syncthreads();
        if (tid < 32) {
            float a = arr[tid] + arr[tid + 32];
            #pragma unroll
            for (int o = 16; o > 0; o >>= 1) a += __shfl_down_sync(0xffffffffu, a, o);
            if (tid == 0) hres[2] = a;
        }
        __syncthreads();
        if (tid < 64) arr[tid] = tvs[tid] * x0s[tid];
        __syncthreads();
        if (tid < 32) {
            float a = arr[tid] + arr[tid + 32];
            #pragma unroll
            for (int o = 16; o > 0; o >>= 1) a += __shfl_down_sync(0xffffffffu, a, o);
            if (tid == 0) hres[3] = a;
        }
        __syncthreads();

        if (tid == 0) {
            g_su[h]  = hres[1];
            g_gam[h] = hres[2] + hres[0];
            g_sc0[h] = 32.0f * (hres[3] + hres[0]);
        }
        if (tid < 16) {   // vproj
            float a = 0.f;
            #pragma unroll 16
            for (int d = 0; d < DHd; d++) a += us[d] * Wp[(h * DHd + d) * 16 + tid];
            g_vproj[h * 16 + tid] = a;
        }
        if (tid < SEQ) {  // pep, pe recomputed inline
            int s = tid;
            float a = 0.f;
            for (int d = 0; d < DHd; d++) {
                int gd = h * DHd + d;
                float sa, ca;
                sincosf((float)s * freqs[d], &sa, &ca);
                a += us[d] * ((gd & 1) ? ca : sa);
            }
            g_pep[h * SEQ + s] = a;
        }
    }
}

// ============================================================================
// K_MAIN: per-batch kernel, BT=4 batch elements per block. 512 threads.
// ============================================================================
// dynamic smem layout (floats)
#define OFF_PA   0                       // [BT][49*16]          3136
#define OFF_SCR  (OFF_PA + BT*784)       // [BT][16*52]          3328
#define OFF_MU   (OFF_SCR + BT*832)      // [BT][50]             200
#define OFF_RSD  (OFF_MU + BT*50)        // [BT][50]             200
#define OFF_QT   (OFF_RSD + BT*50)       // [BT][16*16]          1024
#define OFF_CC   (OFF_QT + BT*256)       // [BT][1024]           4096
#define OFF_T0P  (OFF_CC + BT*1024)      // [BT][1024]           4096
#define OFF_P0   (OFF_T0P + BT*1024)     // [BT*16]              64
#define OFF_MB   (OFF_P0 + BT*16)        // [BT*16]              64
#define OFF_RED2 (OFF_MB + BT*16)        // [16]                 16
#define KMAIN_FLOATS (OFF_RED2 + 16)
#define KMAIN_SMEM (KMAIN_FLOATS * 4)

__global__ __launch_bounds__(512) void k_main(
    const float* __restrict__ x,
    const float* __restrict__ ln1w, const float* __restrict__ ln1b,
    const float* __restrict__ Wv, const float* __restrict__ bv,
    const float* __restrict__ Wp,
    const float* __restrict__ ln2w, const float* __restrict__ ln2b)
{
    extern __shared__ float sm[];
    float* pa    = sm + OFF_PA;
    float* scr   = sm + OFF_SCR;
    float* mu    = sm + OFF_MU;
    float* rsd   = sm + OFF_RSD;
    float* qt    = sm + OFF_QT;
    float* cc    = sm + OFF_CC;
    float* t0p   = sm + OFF_T0P;
    float* p0s   = sm + OFF_P0;
    float* mbars = sm + OFF_MB;
    float* red   = sm + OFF_RED2;

    const int b0  = blockIdx.x * BT;
    const int tid = threadIdx.x;
    const int w = tid >> 5, lane = tid & 31;

    // Phase 1: patchify BT images
    if (tid < BT) { mu[tid * 50] = 0.f; rsd[tid * 50] = 0.f; }
    for (int idx = tid; idx < BT * 784; idx += 512) {
        int bt = idx / 784, r = idx % 784;
        int row = r / 28, col = r % 28;
        int pi = (row >> 2) * 7 + (col >> 2);
        int pp = (row & 3) * 4 + (col & 3);
        pa[bt * 784 + pi * 16 + pp] = x[(size_t)(b0 + bt) * 784 + r];
    }
    __syncthreads();

    // Phase 2: LN stats via quadratic form; 16-lane group per token
    for (int t = w * 2 + (lane >> 4); t < BT * 49; t += 32) {
        int bt = t / 49, sidx = t % 49, s = sidx + 1;
        int p = lane & 15;
        const float* pr = &pa[bt * 784 + sidx * 16];
        float pap = pr[p];
        float y = 0.f;
        #pragma unroll
        for (int q = 0; q < 16; q++) y += g_G[p * 16 + q] * pr[q];
        float e2p = pap * (y + 2.0f * g_hh[s * 16 + p]);
        float mup = pap * g_cs[p];
        #pragma unroll
        for (int o = 8; o > 0; o >>= 1) {
            e2p += __shfl_down_sync(0xffffffffu, e2p, o, 16);
            mup += __shfl_down_sync(0xffffffffu, mup, o, 16);
        }
        if (p == 0) {
            float m = (mup + g_pesum[s]) * (1.0f / (float)Dm);
            float var = (e2p + g_pesq[s]) * (1.0f / (float)Dm) - m * m;
            mu[bt * 50 + s] = m;
            rsd[bt * 50 + s] = rsqrtf(var + LNEPS);
        }
    }
    __syncthreads();

    // Phase 3: scores for all (bt, h, s)
    for (int t = tid; t < BT * NH * SEQ; t += 512) {
        int bt = t / (NH * SEQ), rem = t % (NH * SEQ);
        int h = rem / SEQ, s = rem % SEQ;
        float v;
        if (s == 0) {
            v = g_sc0[h];
        } else {
            float g = g_pep[h * SEQ + s];
            const float* pr = &pa[bt * 784 + (s - 1) * 16];
            const float* vp = &g_vproj[h * 16];
            #pragma unroll
            for (int p = 0; p < 16; p++) g += pr[p] * vp[p];
            v = 32.0f * (rsd[bt * 50 + s] * (g - mu[bt * 50 + s] * g_su[h]) + g_gam[h]);
        }
        scr[bt * 832 + h * 52 + s] = v;
    }
    __syncthreads();

    // Phase 4: softmax per (bt,h); rr (= p_s * rstd_s) written in place
    for (int task = w; task < BT * NH; task += 16) {
        int bt = task >> 4, h = task & 15;
        float* row = &scr[bt * 832 + h * 52];
        float v1 = row[lane];
        float v2 = (lane + 32 < SEQ) ? row[lane + 32] : -INFINITY;
        float m = fmaxf(v1, v2);
        #pragma unroll
        for (int o = 16; o > 0; o >>= 1) m = fmaxf(m, __shfl_xor_sync(0xffffffffu, m, o));
        float e1 = expf(v1 - m);
        float e2 = (lane + 32 < SEQ) ? expf(v2 - m) : 0.f;
        float ss = e1 + e2;
        #pragma unroll
        for (int o = 16; o > 0; o >>= 1) ss += __shfl_xor_sync(0xffffffffu, ss, o);
        float inv = 1.0f / ss;
        float p1 = e1 * inv, p2 = e2 * inv;
        float r1 = (lane == 0) ? 0.f : p1 * rsd[bt * 50 + lane];
        float r2 = (lane + 32 < SEQ) ? p2 * rsd[bt * 50 + lane + 32] : 0.f;
        row[lane] = r1;
        if (lane + 32 < SEQ) row[lane + 32] = r2;
        float mb = r1 * mu[bt * 50 + lane]
                 + ((lane + 32 < SEQ) ? r2 * mu[bt * 50 + lane + 32] : 0.f);
        #pragma unroll
        for (int o = 16; o > 0; o >>= 1) mb += __shfl_xor_sync(0xffffffffu, mb, o);
        if (lane == 0) { mbars[bt * 16 + h] = mb; p0s[bt * 16 + h] = p1; }
    }
    __syncthreads();

    // Phase 5: weighted patch sums qt
    for (int task = w; task < BT * NH; task += 16) {
        int bt = task >> 4, h = task & 15;
        if (lane < 16) {
            int p = lane;
            const float* rr = &scr[bt * 832 + h * 52];
            const float* pb = &pa[bt * 784];
            float a = 0.f;
            #pragma unroll 7
            for (int sidx = 0; sidx < 49; sidx++)
                a += rr[sidx + 1] * pb[sidx * 16 + p];
            qt[bt * 256 + h * 16 + p] = a;
        }
    }
    __syncthreads();

    // Phase 6: context vectors (weights loaded once, BT accumulators)
    for (int gd = tid; gd < Dm; gd += 512) {
        int h = gd >> 6;
        float t1[BT], t2[BT];
        #pragma unroll
        for (int bt = 0; bt < BT; bt++) { t1[bt] = 0.f; t2[bt] = 0.f; }
        #pragma unroll
        for (int p = 0; p < 16; p++) {
            float wv = Wp[gd * 16 + p];
            #pragma unroll
            for (int bt = 0; bt < BT; bt++)
                t1[bt] += qt[bt * 256 + h * 16 + p] * wv;
        }
        #pragma unroll 7
        for (int s = 1; s < SEQ; s++) {
            float pev = g_pe[s * Dm + gd];
            #pragma unroll
            for (int bt = 0; bt < BT; bt++)
                t2[bt] += scr[bt * 832 + h * 52 + s] * pev;
        }
        float w1 = ln1w[gd], bb = ln1b[gd], xx0 = g_x0[gd];
        #pragma unroll
        for (int bt = 0; bt < BT; bt++) {
            float p0 = p0s[bt * 16 + h];
            cc[bt * 1024 + gd] = w1 * (t1[bt] + t2[bt] - mbars[bt * 16 + h])
                               + (1.0f - p0) * bb + p0 * xx0;
        }
    }
    __syncthreads();

    // Phase 7: out = Wv c + bv ; residual with tok0
    for (int ge = tid; ge < Dm; ge += 512) {
        int h = ge >> 6;
        float a[BT];
        float bve = bv[ge];
        #pragma unroll
        for (int bt = 0; bt < BT; bt++) a[bt] = bve;
        const float* wr = &Wv[(size_t)ge * DHd];
        #pragma unroll 8
        for (int d = 0; d < DHd; d++) {
            float wvd = wr[d];
            #pragma unroll
            for (int bt = 0; bt < BT; bt++)
                a[bt] += wvd * cc[bt * 1024 + h * DHd + d];
        }
        float tk0 = g_tok0[ge];
        #pragma unroll
        for (int bt = 0; bt < BT; bt++)
            t0p[bt * 1024 + ge] = tk0 + a[bt];
    }
    __syncthreads();

    // Phase 8: LN2 per bt, write outputs
    for (int bt = 0; bt < BT; bt++) {
        float v0 = t0p[bt * 1024 + tid], v1 = t0p[bt * 1024 + tid + 512];
        float s = bred_generic(v0 + v1, red, 16);
        float m = s * (1.0f / (float)Dm);
        float d0 = v0 - m, d1 = v1 - m;
        float q = bred_generic(d0 * d0 + d1 * d1, red, 16);
        float rstd = rsqrtf(q * (1.0f / (float)Dm) + LNEPS);
        size_t base = (size_t)(b0 + bt) * Dm;
        g_tok0p[base + tid]       = v0;
        g_tok0p[base + tid + 512] = v1;
        g_n0[base + tid]       = d0 * rstd * ln2w[tid] + ln2b[tid];
        g_n0[base + tid + 512] = d1 * rstd * ln2w[tid + 512] + ln2b[tid + 512];
    }
}

// ---------------- GEMM: C = A * Bw^T + bias (+ Res) --------------------------
template <bool HAS_RES>
__global__ __launch_bounds__(256) void gemm_nt_kernel(
    const float* __restrict__ A, const float* __restrict__ Bw,
    const float* __restrict__ bias, const float* __restrict__ Res,
    float* __restrict__ C, int M, int N, int K)
{
    __shared__ float As[16][68];
    __shared__ float Bs[16][68];
    int m0 = blockIdx.y * 64, n0 = blockIdx.x * 64;
    int tid = threadIdx.x;
    int lr = tid >> 2;
    int lq = tid & 3;
    int tx = tid & 15, ty = tid >> 4;
    float acc[4][4] = {};

    for (int k0 = 0; k0 < K; k0 += 16) {
        float4 av = *(const float4*)&A[(size_t)(m0 + lr) * K + k0 + lq * 4];
        float4 bv4 = make_float4(0.f, 0.f, 0.f, 0.f);
        int nr = n0 + lr;
        if (nr < N) bv4 = *(const float4*)&Bw[(size_t)nr * K + k0 + lq * 4];
        As[lq * 4 + 0][lr] = av.x;  As[lq * 4 + 1][lr] = av.y;
        As[lq * 4 + 2][lr] = av.z;  As[lq * 4 + 3][lr] = av.w;
        Bs[lq * 4 + 0][lr] = bv4.x; Bs[lq * 4 + 1][lr] = bv4.y;
        Bs[lq * 4 + 2][lr] = bv4.z; Bs[lq * 4 + 3][lr] = bv4.w;
        __syncthreads();
        #pragma unroll
        for (int k = 0; k < 16; k++) {
            float4 ar = *(const float4*)&As[k][ty * 4];
            float4 br = *(const float4*)&Bs[k][tx * 4];
            float arr[4] = {ar.x, ar.y, ar.z, ar.w};
            float brr[4] = {br.x, br.y, br.z, br.w};
            #pragma unroll
            for (int i = 0; i < 4; i++)
                #pragma unroll
                for (int j = 0; j < 4; j++) acc[i][j] += arr[i] * brr[j];
        }
        __syncthreads();
    }
    #pragma unroll
    for (int i = 0; i < 4; i++) {
        int m = m0 + ty * 4 + i;
        #pragma unroll
        for (int j = 0; j < 4; j++) {
            int nn = n0 + tx * 4 + j;
            if (nn < N) {
                float v = acc[i][j] + bias[nn];
                if (HAS_RES) v += Res[(size_t)m * N + nn];
                C[(size_t)m * N + nn] = v;
            }
        }
    }
}

// ---------------- softmax over 1000 logits -----------------------------------
__global__ __launch_bounds__(256) void softmax_kernel(float* __restrict__ out) {
    int b = blockIdx.x, tid = threadIdx.x;
    __shared__ float red[32];
    int lane = tid & 31, w = tid >> 5;
    float v[4];
    float m = -INFINITY;
    #pragma unroll
    for (int u = 0; u < 4; u++) {
        int j = tid + 256 * u;
        v[u] = (j < NOUT) ? out[(size_t)b * NOUT + j] : -INFINITY;
        m = fmaxf(m, v[u]);
    }
    #pragma unroll
    for (int o = 16; o > 0; o >>= 1) m = fmaxf(m, __shfl_xor_sync(0xffffffffu, m, o));
    if (lane == 0) red[w] = m;
    __syncthreads();
    if (tid < 8) {
        float x2 = red[tid];
        #pragma unroll
        for (int o = 4; o > 0; o >>= 1) x2 = fmaxf(x2, __shfl_xor_sync(0xffu, x2, o));
        if (tid == 0) red[0] = x2;
    }
    __syncthreads();
    m = red[0];
    __syncthreads();
    float s = 0.f;
    #pragma unroll
    for (int u = 0; u < 4; u++) {
        int j = tid + 256 * u;
        if (j < NOUT) { v[u] = expf(v[u] - m); s += v[u]; }
    }
    #pragma unroll
    for (int o = 16; o > 0; o >>= 1) s += __shfl_xor_sync(0xffffffffu, s, o);
    if (lane == 0) red[w] = s;
    __syncthreads();
    if (tid < 8) {
        float x2 = red[tid];
        #pragma unroll
        for (int o = 4; o > 0; o >>= 1) x2 += __shfl_xor_sync(0xffu, x2, o);
        if (tid == 0) red[0] = x2;
    }
    __syncthreads();
    float inv = 1.0f / red[0];
    #pragma unroll
    for (int u = 0; u < 4; u++) {
        int j = tid + 256 * u;
        if (j < NOUT) out[(size_t)b * NOUT + j] = v[u] * inv;
    }
}

// ---------------- launch ------------------------------------------------------
extern "C" void kernel_launch(void* const* d_in, const int* in_sizes, int n_in,
                              void* d_out, int out_size) {
    const float* x    = (const float*)d_in[0];
    const float* cls  = (const float*)d_in[1];
    const float* Wp   = (const float*)d_in[2];
    const float* ln1w = (const float*)d_in[3];
    const float* ln1b = (const float*)d_in[4];
    const float* Wq   = (const float*)d_in[5];
    const float* bq   = (const float*)d_in[6];
    const float* Wk   = (const float*)d_in[7];
    const float* bk   = (const float*)d_in[8];
    const float* Wv   = (const float*)d_in[9];
    const float* bv   = (const float*)d_in[10];
    const float* ln2w = (const float*)d_in[11];
    const float* ln2b = (const float*)d_in[12];
    const float* Wm   = (const float*)d_in[13];
    const float* bm   = (const float*)d_in[14];
    const float* Wh   = (const float*)d_in[15];
    const float* bh   = (const float*)d_in[16];
    float* out = (float*)d_out;

    float *p_n0 = nullptr, *p_tok0p = nullptr, *p_final = nullptr;
    cudaGetSymbolAddress((void**)&p_n0, g_n0);
    cudaGetSymbolAddress((void**)&p_tok0p, g_tok0p);
    cudaGetSymbolAddress((void**)&p_final, g_final);

    cudaFuncSetAttribute(k_main, cudaFuncAttributeMaxDynamicSharedMemorySize,
                         KMAIN_SMEM);

    k_pre<<<83, 256>>>(Wp, cls, ln1w, ln1b, Wq, bq, Wk, bk);
    k_main<<<Bsz / BT, 512, KMAIN_SMEM>>>(x, ln1w, ln1b, Wv, bv, Wp, ln2w, ln2b);
    gemm_nt_kernel<true><<<dim3(Dm / 64, Bsz / 64), 256>>>(
        p_n0, Wm, bm, p_tok0p, p_final, Bsz, Dm, Dm);
    gemm_nt_kernel<false><<<dim3((NOUT + 63) / 64, Bsz / 64), 256>>>(
        p_final, Wh, bh, nullptr, out, Bsz, NOUT, Dm);
    softmax_kernel<<<Bsz, 256>>>(out);
}

// round 5
// speedup vs baseline: 7.8334x; 1.0581x over previous
#include <cuda_runtime.h>
#include <math.h>

#define Bsz 1024
#define Dm 1024
#define NH 16
#define DHd 64
#define SEQ 50
#define NOUT 1000
#define LNEPS 1e-5f
#define BT 4                      // batch elements per k_main block

// ---------------- scratch globals ------------------------------------------
__device__ float g_pe[SEQ * Dm];      // pos-emb table
__device__ float g_hh[SEQ * 16];      // Wp^T pe_s
__device__ float g_pesum[SEQ];
__device__ float g_pesq[SEQ];
__device__ float g_G[256];            // Wp^T Wp
__device__ float g_cs[16];            // col sums of Wp
__device__ float g_x0[Dm];            // LN1(cls+pe0)
__device__ float g_tok0[Dm];          // cls+pe0
__device__ float g_vproj[NH * 16];    // Wp^T u_h
__device__ float g_pep[NH * SEQ];     // pe^T u_h
__device__ float g_su[NH];
__device__ float g_gam[NH];
__device__ float g_sc0[NH];
__device__ float g_tok0p[Bsz * Dm];
__device__ float g_n0[Bsz * Dm];
__device__ float g_final[Bsz * Dm];

// ---------------- reduce helpers --------------------------------------------
__device__ __forceinline__ float bred256(float v, float* red) {
    int tid = threadIdx.x, lane = tid & 31, w = tid >> 5;
    #pragma unroll
    for (int o = 16; o > 0; o >>= 1) v += __shfl_xor_sync(0xffffffffu, v, o);
    if (lane == 0) red[w] = v;
    __syncthreads();
    float r = 0.f;
    if (tid < 8) {
        r = red[tid];
        #pragma unroll
        for (int o = 4; o > 0; o >>= 1) r += __shfl_xor_sync(0xffu, r, o);
        if (tid == 0) red[0] = r;
    }
    __syncthreads();
    r = red[0];
    __syncthreads();
    return r;
}

__device__ __forceinline__ float bred_generic(float v, float* red, int nwarps) {
    int tid = threadIdx.x, lane = tid & 31, w = tid >> 5;
    #pragma unroll
    for (int o = 16; o > 0; o >>= 1) v += __shfl_xor_sync(0xffffffffu, v, o);
    if (lane == 0) red[w] = v;
    __syncthreads();
    float r = 0.f;
    if (tid < 32) {
        r = (tid < nwarps) ? red[tid] : 0.f;
        #pragma unroll
        for (int o = 16; o > 0; o >>= 1) r += __shfl_xor_sync(0xffffffffu, r, o);
        if (tid == 0) red[0] = r;
    }
    __syncthreads();
    r = red[0];
    __syncthreads();
    return r;
}

// ============================================================================
// K_PRE: ALL batch-independent precompute in one kernel, 83 independent blocks
// ============================================================================
__global__ __launch_bounds__(256) void k_pre(
    const float* __restrict__ Wp, const float* __restrict__ cls,
    const float* __restrict__ ln1w, const float* __restrict__ ln1b,
    const float* __restrict__ Wq, const float* __restrict__ bq,
    const float* __restrict__ Wk, const float* __restrict__ bk)
{
    __shared__ float red[8];
    __shared__ float x0s[64], q0s[64], tvs[64], us[64], arr[64], freqs[64];
    __shared__ float hres[4];
    const int bid = blockIdx.x, tid = threadIdx.x;

    if (bid < 50) {                       // ---- pe row s ----
        int s = bid;
        float v[4];
        #pragma unroll
        for (int u = 0; u < 4; u++) {
            int d = tid + 256 * u;
            float freq = powf(10000.f, -(float)(d & ~1) / (float)Dm);
            float sa, ca;
            sincosf((float)s * freq, &sa, &ca);
            float p = (d & 1) ? ca : sa;
            g_pe[s * Dm + d] = p;
            v[u] = p;
        }
        float ps = bred256(v[0] + v[1] + v[2] + v[3], red);
        float pq = bred256(v[0]*v[0] + v[1]*v[1] + v[2]*v[2] + v[3]*v[3], red);
        if (tid == 0) { g_pesum[s] = ps; g_pesq[s] = pq; }
        for (int p = 0; p < 16; p++) {
            float a = 0.f;
            #pragma unroll
            for (int u = 0; u < 4; u++) a += Wp[(tid + 256 * u) * 16 + p] * v[u];
            float r = bred256(a, red);
            if (tid == 0) g_hh[s * 16 + p] = r;
        }
    } else if (bid < 66) {                // ---- Gram column p ----
        int p = bid - 50;
        float acc[16];
        #pragma unroll
        for (int q = 0; q < 16; q++) acc[q] = 0.f;
        float cs = 0.f;
        for (int d = tid; d < Dm; d += 256) {
            float wdp = Wp[d * 16 + p];
            cs += wdp;
            #pragma unroll
            for (int q = 0; q < 16; q++) acc[q] += wdp * Wp[d * 16 + q];
        }
        for (int q = 0; q < 16; q++) {
            float r = bred256(acc[q], red);
            if (tid == 0) g_G[p * 16 + q] = r;
        }
        float r = bred256(cs, red);
        if (tid == 0) g_cs[p] = r;
    } else if (bid == 66) {               // ---- tok0 + LN1(tok0) ----
        float v[4];
        float s1 = 0.f;
        #pragma unroll
        for (int u = 0; u < 4; u++) {
            int d = tid + 256 * u;
            float pe0 = (d & 1) ? 1.f : 0.f;
            v[u] = cls[d] + pe0;
            g_tok0[d] = v[u];
            s1 += v[u];
        }
        float mu = bred256(s1, red) * (1.0f / (float)Dm);
        float s2 = 0.f;
        #pragma unroll
        for (int u = 0; u < 4; u++) { float dv = v[u] - mu; s2 += dv * dv; }
        float var = bred256(s2, red) * (1.0f / (float)Dm);
        float rstd = rsqrtf(var + LNEPS);
        #pragma unroll
        for (int u = 0; u < 4; u++) {
            int d = tid + 256 * u;
            g_x0[d] = (v[u] - mu) * rstd * ln1w[d] + ln1b[d];
        }
    } else {                              // ---- per-head precompute ----
        int h = bid - 67;
        float s1 = 0.f;
        #pragma unroll
        for (int u = 0; u < 4; u++) {
            int d = tid + 256 * u;
            s1 += cls[d] + ((d & 1) ? 1.f : 0.f);
        }
        float mu = bred256(s1, red) * (1.0f / (float)Dm);
        float s2 = 0.f;
        #pragma unroll
        for (int u = 0; u < 4; u++) {
            int d = tid + 256 * u;
            float dv = cls[d] + ((d & 1) ? 1.f : 0.f) - mu;
            s2 += dv * dv;
        }
        float var = bred256(s2, red) * (1.0f / (float)Dm);
        float rstd = rsqrtf(var + LNEPS);

        if (tid < 64) {
            int gd = h * DHd + tid;
            float val = cls[gd] + ((gd & 1) ? 1.f : 0.f);
            x0s[tid] = (val - mu) * rstd * ln1w[gd] + ln1b[gd];
            freqs[tid] = powf(10000.f, -(float)(gd & ~1) / (float)Dm);
        }
        __syncthreads();

        if (tid < 64) {   // q0
            float a = bq[h * DHd + tid];
            const float* wr = &Wq[(h * DHd + tid) * DHd];
            #pragma unroll 16
            for (int d = 0; d < DHd; d++) a += wr[d] * x0s[d];
            q0s[tid] = a;
        }
        __syncthreads();

        if (tid < 64) arr[tid] = q0s[tid] * bk[h * DHd + tid];
        __syncthreads();
        if (tid < 32) {
            float a = arr[tid] + arr[tid + 32];
            #pragma unroll
            for (int o = 16; o > 0; o >>= 1) a += __shfl_down_sync(0xffffffffu, a, o);
            if (tid == 0) hres[0] = a;
        }
        __syncthreads();

        if (tid < 64) {   // tv = Wk^T q0, u = tv*ln1w
            float a = 0.f;
            #pragma unroll 16
            for (int d = 0; d < DHd; d++) a += q0s[d] * Wk[(h * DHd + d) * DHd + tid];
            tvs[tid] = a;
            us[tid] = a * ln1w[h * DHd + tid];
        }
        __syncthreads();

        if (tid < 64) arr[tid] = us[tid];
        __syncthreads();
        if (tid < 32) {
            float a = arr[tid] + arr[tid + 32];
            #pragma unroll
            for (int o = 16; o > 0; o >>= 1) a += __shfl_down_sync(0xffffffffu, a, o);
            if (tid == 0) hres[1] = a;
        }
        __syncthreads();
        if (tid < 64) arr[tid] = tvs[tid] * ln1b[h * DHd + tid];
        __syncthreads();
        if (tid < 32) {
            float a = arr[tid] + arr[tid + 32];
            #pragma unroll
            for (int o = 16; o > 0; o >>= 1) a += __shfl_down_sync(0xffffffffu, a, o);
            if (tid == 0) hres[2] = a;
        }
        __syncthreads();
        if (tid < 64) arr[tid] = tvs[tid] * x0s[tid];
        __syncthreads();
        if (tid < 32) {
            float a = arr[tid] + arr[tid + 32];
            #pragma unroll
            for (int o = 16; o > 0; o >>= 1) a += __shfl_down_sync(0xffffffffu, a, o);
            if (tid == 0) hres[3] = a;
        }
        __syncthreads();

        if (tid == 0) {
            g_su[h]  = hres[1];
            g_gam[h] = hres[2] + hres[0];
            g_sc0[h] = 32.0f * (hres[3] + hres[0]);
        }
        if (tid < 16) {   // vproj
            float a = 0.f;
            #pragma unroll 16
            for (int d = 0; d < DHd; d++) a += us[d] * Wp[(h * DHd + d) * 16 + tid];
            g_vproj[h * 16 + tid] = a;
        }
        if (tid < SEQ) {  // pep
            int s = tid;
            float a = 0.f;
            for (int d = 0; d < DHd; d++) {
                int gd = h * DHd + d;
                float sa, ca;
                sincosf((float)s * freqs[d], &sa, &ca);
                a += us[d] * ((gd & 1) ? ca : sa);
            }
            g_pep[h * SEQ + s] = a;
        }
    }
}

// ============================================================================
// K_MAIN: per-batch kernel, BT=4 batch elements per block. 512 threads.
// ============================================================================
#define OFF_PA   0
#define OFF_SCR  (OFF_PA + BT*784)
#define OFF_MU   (OFF_SCR + BT*832)
#define OFF_RSD  (OFF_MU + BT*50)
#define OFF_QT   (OFF_RSD + BT*50)
#define OFF_CC   (OFF_QT + BT*256)
#define OFF_T0P  (OFF_CC + BT*1024)
#define OFF_P0   (OFF_T0P + BT*1024)
#define OFF_MB   (OFF_P0 + BT*16)
#define OFF_RED2 (OFF_MB + BT*16)
#define KMAIN_FLOATS (OFF_RED2 + 16)
#define KMAIN_SMEM (KMAIN_FLOATS * 4)

__global__ __launch_bounds__(512) void k_main(
    const float* __restrict__ x,
    const float* __restrict__ ln1w, const float* __restrict__ ln1b,
    const float* __restrict__ Wv, const float* __restrict__ bv,
    const float* __restrict__ Wp,
    const float* __restrict__ ln2w, const float* __restrict__ ln2b)
{
    extern __shared__ float sm[];
    float* pa    = sm + OFF_PA;
    float* scr   = sm + OFF_SCR;
    float* mu    = sm + OFF_MU;
    float* rsd   = sm + OFF_RSD;
    float* qt    = sm + OFF_QT;
    float* cc    = sm + OFF_CC;
    float* t0p   = sm + OFF_T0P;
    float* p0s   = sm + OFF_P0;
    float* mbars = sm + OFF_MB;
    float* red   = sm + OFF_RED2;

    const int b0  = blockIdx.x * BT;
    const int tid = threadIdx.x;
    const int w = tid >> 5, lane = tid & 31;

    if (tid < BT) { mu[tid * 50] = 0.f; rsd[tid * 50] = 0.f; }
    for (int idx = tid; idx < BT * 784; idx += 512) {
        int bt = idx / 784, r = idx % 784;
        int row = r / 28, col = r % 28;
        int pi = (row >> 2) * 7 + (col >> 2);
        int pp = (row & 3) * 4 + (col & 3);
        pa[bt * 784 + pi * 16 + pp] = x[(size_t)(b0 + bt) * 784 + r];
    }
    __syncthreads();

    for (int t = w * 2 + (lane >> 4); t < BT * 49; t += 32) {
        int bt = t / 49, sidx = t % 49, s = sidx + 1;
        int p = lane & 15;
        const float* pr = &pa[bt * 784 + sidx * 16];
        float pap = pr[p];
        float y = 0.f;
        #pragma unroll
        for (int q = 0; q < 16; q++) y += g_G[p * 16 + q] * pr[q];
        float e2p = pap * (y + 2.0f * g_hh[s * 16 + p]);
        float mup = pap * g_cs[p];
        #pragma unroll
        for (int o = 8; o > 0; o >>= 1) {
            e2p += __shfl_down_sync(0xffffffffu, e2p, o, 16);
            mup += __shfl_down_sync(0xffffffffu, mup, o, 16);
        }
        if (p == 0) {
            float m = (mup + g_pesum[s]) * (1.0f / (float)Dm);
            float var = (e2p + g_pesq[s]) * (1.0f / (float)Dm) - m * m;
            mu[bt * 50 + s] = m;
            rsd[bt * 50 + s] = rsqrtf(var + LNEPS);
        }
    }
    __syncthreads();

    for (int t = tid; t < BT * NH * SEQ; t += 512) {
        int bt = t / (NH * SEQ), rem = t % (NH * SEQ);
        int h = rem / SEQ, s = rem % SEQ;
        float v;
        if (s == 0) {
            v = g_sc0[h];
        } else {
            float g = g_pep[h * SEQ + s];
            const float* pr = &pa[bt * 784 + (s - 1) * 16];
            const float* vp = &g_vproj[h * 16];
            #pragma unroll
            for (int p = 0; p < 16; p++) g += pr[p] * vp[p];
            v = 32.0f * (rsd[bt * 50 + s] * (g - mu[bt * 50 + s] * g_su[h]) + g_gam[h]);
        }
        scr[bt * 832 + h * 52 + s] = v;
    }
    __syncthreads();

    for (int task = w; task < BT * NH; task += 16) {
        int bt = task >> 4, h = task & 15;
        float* row = &scr[bt * 832 + h * 52];
        float v1 = row[lane];
        float v2 = (lane + 32 < SEQ) ? row[lane + 32] : -INFINITY;
        float m = fmaxf(v1, v2);
        #pragma unroll
        for (int o = 16; o > 0; o >>= 1) m = fmaxf(m, __shfl_xor_sync(0xffffffffu, m, o));
        float e1 = expf(v1 - m);
        float e2 = (lane + 32 < SEQ) ? expf(v2 - m) : 0.f;
        float ss = e1 + e2;
        #pragma unroll
        for (int o = 16; o > 0; o >>= 1) ss += __shfl_xor_sync(0xffffffffu, ss, o);
        float inv = 1.0f / ss;
        float p1 = e1 * inv, p2 = e2 * inv;
        float r1 = (lane == 0) ? 0.f : p1 * rsd[bt * 50 + lane];
        float r2 = (lane + 32 < SEQ) ? p2 * rsd[bt * 50 + lane + 32] : 0.f;
        row[lane] = r1;
        if (lane + 32 < SEQ) row[lane + 32] = r2;
        float mb = r1 * mu[bt * 50 + lane]
                 + ((lane + 32 < SEQ) ? r2 * mu[bt * 50 + lane + 32] : 0.f);
        #pragma unroll
        for (int o = 16; o > 0; o >>= 1) mb += __shfl_xor_sync(0xffffffffu, mb, o);
        if (lane == 0) { mbars[bt * 16 + h] = mb; p0s[bt * 16 + h] = p1; }
    }
    __syncthreads();

    for (int task = w; task < BT * NH; task += 16) {
        int bt = task >> 4, h = task & 15;
        if (lane < 16) {
            int p = lane;
            const float* rr = &scr[bt * 832 + h * 52];
            const float* pb = &pa[bt * 784];
            float a = 0.f;
            #pragma unroll 7
            for (int sidx = 0; sidx < 49; sidx++)
                a += rr[sidx + 1] * pb[sidx * 16 + p];
            qt[bt * 256 + h * 16 + p] = a;
        }
    }
    __syncthreads();

    for (int gd = tid; gd < Dm; gd += 512) {
        int h = gd >> 6;
        float t1[BT], t2[BT];
        #pragma unroll
        for (int bt = 0; bt < BT; bt++) { t1[bt] = 0.f; t2[bt] = 0.f; }
        #pragma unroll
        for (int p = 0; p < 16; p++) {
            float wv = Wp[gd * 16 + p];
            #pragma unroll
            for (int bt = 0; bt < BT; bt++)
                t1[bt] += qt[bt * 256 + h * 16 + p] * wv;
        }
        #pragma unroll 7
        for (int s = 1; s < SEQ; s++) {
            float pev = g_pe[s * Dm + gd];
            #pragma unroll
            for (int bt = 0; bt < BT; bt++)
                t2[bt] += scr[bt * 832 + h * 52 + s] * pev;
        }
        float w1 = ln1w[gd], bb = ln1b[gd], xx0 = g_x0[gd];
        #pragma unroll
        for (int bt = 0; bt < BT; bt++) {
            float p0 = p0s[bt * 16 + h];
            cc[bt * 1024 + gd] = w1 * (t1[bt] + t2[bt] - mbars[bt * 16 + h])
                               + (1.0f - p0) * bb + p0 * xx0;
        }
    }
    __syncthreads();

    for (int ge = tid; ge < Dm; ge += 512) {
        int h = ge >> 6;
        float a[BT];
        float bve = bv[ge];
        #pragma unroll
        for (int bt = 0; bt < BT; bt++) a[bt] = bve;
        const float* wr = &Wv[(size_t)ge * DHd];
        #pragma unroll 8
        for (int d = 0; d < DHd; d++) {
            float wvd = wr[d];
            #pragma unroll
            for (int bt = 0; bt < BT; bt++)
                a[bt] += wvd * cc[bt * 1024 + h * DHd + d];
        }
        float tk0 = g_tok0[ge];
        #pragma unroll
        for (int bt = 0; bt < BT; bt++)
            t0p[bt * 1024 + ge] = tk0 + a[bt];
    }
    __syncthreads();

    for (int bt = 0; bt < BT; bt++) {
        float v0 = t0p[bt * 1024 + tid], v1 = t0p[bt * 1024 + tid + 512];
        float s = bred_generic(v0 + v1, red, 16);
        float m = s * (1.0f / (float)Dm);
        float d0 = v0 - m, d1 = v1 - m;
        float q = bred_generic(d0 * d0 + d1 * d1, red, 16);
        float rstd = rsqrtf(q * (1.0f / (float)Dm) + LNEPS);
        size_t base = (size_t)(b0 + bt) * Dm;
        g_tok0p[base + tid]       = v0;
        g_tok0p[base + tid + 512] = v1;
        g_n0[base + tid]       = d0 * rstd * ln2w[tid] + ln2b[tid];
        g_n0[base + tid + 512] = d1 * rstd * ln2w[tid + 512] + ln2b[tid + 512];
    }
}

// ============================================================================
// GEMM: C = A * Bw^T + bias (+ Res). 128x64 tile, BK=16, 256 thr, 8x4 micro.
// ============================================================================
template <bool HAS_RES>
__global__ __launch_bounds__(256) void gemm_nt_kernel(
    const float* __restrict__ A, const float* __restrict__ Bw,
    const float* __restrict__ bias, const float* __restrict__ Res,
    float* __restrict__ C, int M, int N, int K)
{
    __shared__ float As[16][132];   // k-major, padded
    __shared__ float Bs[16][68];
    const int m0 = blockIdx.y * 128, n0 = blockIdx.x * 64;
    const int tid = threadIdx.x;
    const int la_m = tid >> 2;          // 0..63
    const int la_k = (tid & 3) * 4;     // 0,4,8,12
    const int tx = tid & 15;            // n: 4 each
    const int ty = tid >> 4;            // m: 8 each
    float acc[8][4] = {};

    const float* Arow0 = &A[(size_t)(m0 + la_m) * K + la_k];
    const float* Arow1 = &A[(size_t)(m0 + la_m + 64) * K + la_k];
    const int nrow = n0 + la_m;
    const float* Brow = &Bw[(size_t)nrow * K + la_k];
    const bool bok = (nrow < N);

    for (int k0 = 0; k0 < K; k0 += 16) {
        float4 a0 = *(const float4*)&Arow0[k0];
        float4 a1 = *(const float4*)&Arow1[k0];
        float4 b0 = make_float4(0.f, 0.f, 0.f, 0.f);
        if (bok) b0 = *(const float4*)&Brow[k0];
        __syncthreads();
        As[la_k + 0][la_m] = a0.x;  As[la_k + 1][la_m] = a0.y;
        As[la_k + 2][la_m] = a0.z;  As[la_k + 3][la_m] = a0.w;
        As[la_k + 0][la_m + 64] = a1.x;  As[la_k + 1][la_m + 64] = a1.y;
        As[la_k + 2][la_m + 64] = a1.z;  As[la_k + 3][la_m + 64] = a1.w;
        Bs[la_k + 0][la_m] = b0.x;  Bs[la_k + 1][la_m] = b0.y;
        Bs[la_k + 2][la_m] = b0.z;  Bs[la_k + 3][la_m] = b0.w;
        __syncthreads();
        #pragma unroll
        for (int k = 0; k < 16; k++) {
            float4 alo = *(const float4*)&As[k][ty * 8];
            float4 ahi = *(const float4*)&As[k][ty * 8 + 4];
            float4 bf  = *(const float4*)&Bs[k][tx * 4];
            float ar[8] = {alo.x, alo.y, alo.z, alo.w, ahi.x, ahi.y, ahi.z, ahi.w};
            float br[4] = {bf.x, bf.y, bf.z, bf.w};
            #pragma unroll
            for (int i = 0; i < 8; i++)
                #pragma unroll
                for (int j = 0; j < 4; j++) acc[i][j] += ar[i] * br[j];
        }
    }

    // epilogue
    const int nn0 = n0 + tx * 4;
    float4 bias4 = make_float4(0.f, 0.f, 0.f, 0.f);
    if (nn0 + 3 < N) {
        bias4 = *(const float4*)&bias[nn0];
    } else {
        if (nn0 + 0 < N) bias4.x = bias[nn0 + 0];
        if (nn0 + 1 < N) bias4.y = bias[nn0 + 1];
        if (nn0 + 2 < N) bias4.z = bias[nn0 + 2];
    }
    #pragma unroll
    for (int i = 0; i < 8; i++) {
        int m = m0 + ty * 8 + i;
        float4 v = make_float4(acc[i][0] + bias4.x, acc[i][1] + bias4.y,
                               acc[i][2] + bias4.z, acc[i][3] + bias4.w);
        if (nn0 + 3 < N) {
            if (HAS_RES) {
                float4 r = *(const float4*)&Res[(size_t)m * N + nn0];
                v.x += r.x; v.y += r.y; v.z += r.z; v.w += r.w;
            }
            *(float4*)&C[(size_t)m * N + nn0] = v;
        } else {
            float vv[4] = {v.x, v.y, v.z, v.w};
            #pragma unroll
            for (int j = 0; j < 4; j++) {
                int nn = nn0 + j;
                if (nn < N) {
                    float t = vv[j];
                    if (HAS_RES) t += Res[(size_t)m * N + nn];
                    C[(size_t)m * N + nn] = t;
                }
            }
        }
    }
}

// ---------------- softmax over 1000 logits -----------------------------------
__global__ __launch_bounds__(256) void softmax_kernel(float* __restrict__ out) {
    int b = blockIdx.x, tid = threadIdx.x;
    __shared__ float red[32];
    int lane = tid & 31, w = tid >> 5;
    float v[4];
    float m = -INFINITY;
    #pragma unroll
    for (int u = 0; u < 4; u++) {
        int j = tid + 256 * u;
        v[u] = (j < NOUT) ? out[(size_t)b * NOUT + j] : -INFINITY;
        m = fmaxf(m, v[u]);
    }
    #pragma unroll
    for (int o = 16; o > 0; o >>= 1) m = fmaxf(m, __shfl_xor_sync(0xffffffffu, m, o));
    if (lane == 0) red[w] = m;
    __syncthreads();
    if (tid < 8) {
        float x2 = red[tid];
        #pragma unroll
        for (int o = 4; o > 0; o >>= 1) x2 = fmaxf(x2, __shfl_xor_sync(0xffu, x2, o));
        if (tid == 0) red[0] = x2;
    }
    __syncthreads();
    m = red[0];
    __syncthreads();
    float s = 0.f;
    #pragma unroll
    for (int u = 0; u < 4; u++) {
        int j = tid + 256 * u;
        if (j < NOUT) { v[u] = expf(v[u] - m); s += v[u]; }
    }
    #pragma unroll
    for (int o = 16; o > 0; o >>= 1) s += __shfl_xor_sync(0xffffffffu, s, o);
    if (lane == 0) red[w] = s;
    __syncthreads();
    if (tid < 8) {
        float x2 = red[tid];
        #pragma unroll
        for (int o = 4; o > 0; o >>= 1) x2 += __shfl_xor_sync(0xffu, x2, o);
        if (tid == 0) red[0] = x2;
    }
    __syncthreads();
    float inv = 1.0f / red[0];
    #pragma unroll
    for (int u = 0; u < 4; u++) {
        int j = tid + 256 * u;
        if (j < NOUT) out[(size_t)b * NOUT + j] = v[u] * inv;
    }
}

// ---------------- launch ------------------------------------------------------
extern "C" void kernel_launch(void* const* d_in, const int* in_sizes, int n_in,
                              void* d_out, int out_size) {
    const float* x    = (const float*)d_in[0];
    const float* cls  = (const float*)d_in[1];
    const float* Wp   = (const float*)d_in[2];
    const float* ln1w = (const float*)d_in[3];
    const float* ln1b = (const float*)d_in[4];
    const float* Wq   = (const float*)d_in[5];
    const float* bq   = (const float*)d_in[6];
    const float* Wk   = (const float*)d_in[7];
    const float* bk   = (const float*)d_in[8];
    const float* Wv   = (const float*)d_in[9];
    const float* bv   = (const float*)d_in[10];
    const float* ln2w = (const float*)d_in[11];
    const float* ln2b = (const float*)d_in[12];
    const float* Wm   = (const float*)d_in[13];
    const float* bm   = (const float*)d_in[14];
    const float* Wh   = (const float*)d_in[15];
    const float* bh   = (const float*)d_in[16];
    float* out = (float*)d_out;

    float *p_n0 = nullptr, *p_tok0p = nullptr, *p_final = nullptr;
    cudaGetSymbolAddress((void**)&p_n0, g_n0);
    cudaGetSymbolAddress((void**)&p_tok0p, g_tok0p);
    cudaGetSymbolAddress((void**)&p_final, g_final);

    cudaFuncSetAttribute(k_main, cudaFuncAttributeMaxDynamicSharedMemorySize,
                         KMAIN_SMEM);

    k_pre<<<83, 256>>>(Wp, cls, ln1w, ln1b, Wq, bq, Wk, bk);
    k_main<<<Bsz / BT, 512, KMAIN_SMEM>>>(x, ln1w, ln1b, Wv, bv, Wp, ln2w, ln2b);
    gemm_nt_kernel<true><<<dim3(Dm / 64, Bsz / 128), 256>>>(
        p_n0, Wm, bm, p_tok0p, p_final, Bsz, Dm, Dm);
    gemm_nt_kernel<false><<<dim3((NOUT + 63) / 64, Bsz / 128), 256>>>(
        p_final, Wh, bh, nullptr, out, Bsz, NOUT, Dm);
    softmax_kernel<<<Bsz, 256>>>(out);
}

// round 7
// speedup vs baseline: 8.1925x; 1.0458x over previous
#include <cuda_runtime.h>
#include <cstdint>
#include <math.h>

#define Bsz 1024
#define Dm 1024
#define NH 16
#define DHd 64
#define SEQ 50
#define NOUT 1000
#define LNEPS 1e-5f
#define BT 4

// ---------------- scratch globals ------------------------------------------
__device__ float g_pe[SEQ * Dm];
__device__ float g_hh[SEQ * 16];
__device__ float g_pesum[SEQ];
__device__ float g_pesq[SEQ];
__device__ float g_G[256];
__device__ float g_cs[16];
__device__ float g_x0[Dm];
__device__ float g_tok0[Dm];
__device__ float g_vproj[NH * 16];
__device__ float g_pep[NH * SEQ];
__device__ float g_su[NH];
__device__ float g_gam[NH];
__device__ float g_sc0[NH];
__device__ float g_tok0p[Bsz * Dm];
__device__ float g_n0[Bsz * Dm];
__device__ float g_final[Bsz * Dm];

// ---------------- reduce helpers --------------------------------------------
__device__ __forceinline__ float bred256(float v, float* red) {
    int tid = threadIdx.x, lane = tid & 31, w = tid >> 5;
    #pragma unroll
    for (int o = 16; o > 0; o >>= 1) v += __shfl_xor_sync(0xffffffffu, v, o);
    if (lane == 0) red[w] = v;
    __syncthreads();
    float r = 0.f;
    if (tid < 8) {
        r = red[tid];
        #pragma unroll
        for (int o = 4; o > 0; o >>= 1) r += __shfl_xor_sync(0xffu, r, o);
        if (tid == 0) red[0] = r;
    }
    __syncthreads();
    r = red[0];
    __syncthreads();
    return r;
}

__device__ __forceinline__ float bred_generic(float v, float* red, int nwarps) {
    int tid = threadIdx.x, lane = tid & 31, w = tid >> 5;
    #pragma unroll
    for (int o = 16; o > 0; o >>= 1) v += __shfl_xor_sync(0xffffffffu, v, o);
    if (lane == 0) red[w] = v;
    __syncthreads();
    float r = 0.f;
    if (tid < 32) {
        r = (tid < nwarps) ? red[tid] : 0.f;
        #pragma unroll
        for (int o = 16; o > 0; o >>= 1) r += __shfl_xor_sync(0xffffffffu, r, o);
        if (tid == 0) red[0] = r;
    }
    __syncthreads();
    r = red[0];
    __syncthreads();
    return r;
}

// ============================================================================
// K_PRE: batch-independent precompute, 83 independent blocks
// ============================================================================
__global__ __launch_bounds__(256) void k_pre(
    const float* __restrict__ Wp, const float* __restrict__ cls,
    const float* __restrict__ ln1w, const float* __restrict__ ln1b,
    const float* __restrict__ Wq, const float* __restrict__ bq,
    const float* __restrict__ Wk, const float* __restrict__ bk)
{
    __shared__ float red[8];
    __shared__ float x0s[64], q0s[64], tvs[64], us[64], arr[64], freqs[64];
    __shared__ float hres[4];
    const int bid = blockIdx.x, tid = threadIdx.x;

    if (bid < 50) {
        int s = bid;
        float v[4];
        #pragma unroll
        for (int u = 0; u < 4; u++) {
            int d = tid + 256 * u;
            float freq = powf(10000.f, -(float)(d & ~1) / (float)Dm);
            float sa, ca;
            sincosf((float)s * freq, &sa, &ca);
            float p = (d & 1) ? ca : sa;
            g_pe[s * Dm + d] = p;
            v[u] = p;
        }
        float ps = bred256(v[0] + v[1] + v[2] + v[3], red);
        float pq = bred256(v[0]*v[0] + v[1]*v[1] + v[2]*v[2] + v[3]*v[3], red);
        if (tid == 0) { g_pesum[s] = ps; g_pesq[s] = pq; }
        for (int p = 0; p < 16; p++) {
            float a = 0.f;
            #pragma unroll
            for (int u = 0; u < 4; u++) a += Wp[(tid + 256 * u) * 16 + p] * v[u];
            float r = bred256(a, red);
            if (tid == 0) g_hh[s * 16 + p] = r;
        }
    } else if (bid < 66) {
        int p = bid - 50;
        float acc[16];
        #pragma unroll
        for (int q = 0; q < 16; q++) acc[q] = 0.f;
        float cs = 0.f;
        for (int d = tid; d < Dm; d += 256) {
            float wdp = Wp[d * 16 + p];
            cs += wdp;
            #pragma unroll
            for (int q = 0; q < 16; q++) acc[q] += wdp * Wp[d * 16 + q];
        }
        for (int q = 0; q < 16; q++) {
            float r = bred256(acc[q], red);
            if (tid == 0) g_G[p * 16 + q] = r;
        }
        float r = bred256(cs, red);
        if (tid == 0) g_cs[p] = r;
    } else if (bid == 66) {
        float v[4];
        float s1 = 0.f;
        #pragma unroll
        for (int u = 0; u < 4; u++) {
            int d = tid + 256 * u;
            float pe0 = (d & 1) ? 1.f : 0.f;
            v[u] = cls[d] + pe0;
            g_tok0[d] = v[u];
            s1 += v[u];
        }
        float mu = bred256(s1, red) * (1.0f / (float)Dm);
        float s2 = 0.f;
        #pragma unroll
        for (int u = 0; u < 4; u++) { float dv = v[u] - mu; s2 += dv * dv; }
        float var = bred256(s2, red) * (1.0f / (float)Dm);
        float rstd = rsqrtf(var + LNEPS);
        #pragma unroll
        for (int u = 0; u < 4; u++) {
            int d = tid + 256 * u;
            g_x0[d] = (v[u] - mu) * rstd * ln1w[d] + ln1b[d];
        }
    } else {
        int h = bid - 67;
        float s1 = 0.f;
        #pragma unroll
        for (int u = 0; u < 4; u++) {
            int d = tid + 256 * u;
            s1 += cls[d] + ((d & 1) ? 1.f : 0.f);
        }
        float mu = bred256(s1, red) * (1.0f / (float)Dm);
        float s2 = 0.f;
        #pragma unroll
        for (int u = 0; u < 4; u++) {
            int d = tid + 256 * u;
            float dv = cls[d] + ((d & 1) ? 1.f : 0.f) - mu;
            s2 += dv * dv;
        }
        float var = bred256(s2, red) * (1.0f / (float)Dm);
        float rstd = rsqrtf(var + LNEPS);

        if (tid < 64) {
            int gd = h * DHd + tid;
            float val = cls[gd] + ((gd & 1) ? 1.f : 0.f);
            x0s[tid] = (val - mu) * rstd * ln1w[gd] + ln1b[gd];
            freqs[tid] = powf(10000.f, -(float)(gd & ~1) / (float)Dm);
        }
        __syncthreads();

        if (tid < 64) {
            float a = bq[h * DHd + tid];
            const float* wr = &Wq[(h * DHd + tid) * DHd];
            #pragma unroll 16
            for (int d = 0; d < DHd; d++) a += wr[d] * x0s[d];
            q0s[tid] = a;
        }
        __syncthreads();

        if (tid < 64) arr[tid] = q0s[tid] * bk[h * DHd + tid];
        __syncthreads();
        if (tid < 32) {
            float a = arr[tid] + arr[tid + 32];
            #pragma unroll
            for (int o = 16; o > 0; o >>= 1) a += __shfl_down_sync(0xffffffffu, a, o);
            if (tid == 0) hres[0] = a;
        }
        __syncthreads();

        if (tid < 64) {
            float a = 0.f;
            #pragma unroll 16
            for (int d = 0; d < DHd; d++) a += q0s[d] * Wk[(h * DHd + d) * DHd + tid];
            tvs[tid] = a;
            us[tid] = a * ln1w[h * DHd + tid];
        }
        __syncthreads();

        if (tid < 64) arr[tid] = us[tid];
        __syncthreads();
        if (tid < 32) {
            float a = arr[tid] + arr[tid + 32];
            #pragma unroll
            for (int o = 16; o > 0; o >>= 1) a += __shfl_down_sync(0xffffffffu, a, o);
            if (tid == 0) hres[1] = a;
        }
        __syncthreads();
        if (tid < 64) arr[tid] = tvs[tid] * ln1b[h * DHd + tid];
        __syncthreads();
        if (tid < 32) {
            float a = arr[tid] + arr[tid + 32];
            #pragma unroll
            for (int o = 16; o > 0; o >>= 1) a += __shfl_down_sync(0xffffffffu, a, o);
            if (tid == 0) hres[2] = a;
        }
        __syncthreads();
        if (tid < 64) arr[tid] = tvs[tid] * x0s[tid];
        __syncthreads();
        if (tid < 32) {
            float a = arr[tid] + arr[tid + 32];
            #pragma unroll
            for (int o = 16; o > 0; o >>= 1) a += __shfl_down_sync(0xffffffffu, a, o);
            if (tid == 0) hres[3] = a;
        }
        __syncthreads();

        if (tid == 0) {
            g_su[h]  = hres[1];
            g_gam[h] = hres[2] + hres[0];
            g_sc0[h] = 32.0f * (hres[3] + hres[0]);
        }
        if (tid < 16) {
            float a = 0.f;
            #pragma unroll 16
            for (int d = 0; d < DHd; d++) a += us[d] * Wp[(h * DHd + d) * 16 + tid];
            g_vproj[h * 16 + tid] = a;
        }
        if (tid < SEQ) {
            int s = tid;
            float a = 0.f;
            for (int d = 0; d < DHd; d++) {
                int gd = h * DHd + d;
                float sa, ca;
                sincosf((float)s * freqs[d], &sa, &ca);
                a += us[d] * ((gd & 1) ? ca : sa);
            }
            g_pep[h * SEQ + s] = a;
        }
    }
}

// ============================================================================
// K_MAIN: per-batch kernel, BT=4 batch elements per block. 512 threads.
// ============================================================================
#define OFF_PA   0
#define OFF_SCR  (OFF_PA + BT*784)
#define OFF_MU   (OFF_SCR + BT*832)
#define OFF_RSD  (OFF_MU + BT*50)
#define OFF_QT   (OFF_RSD + BT*50)
#define OFF_CC   (OFF_QT + BT*256)
#define OFF_T0P  (OFF_CC + BT*1024)
#define OFF_P0   (OFF_T0P + BT*1024)
#define OFF_MB   (OFF_P0 + BT*16)
#define OFF_RED2 (OFF_MB + BT*16)
#define KMAIN_FLOATS (OFF_RED2 + 16)
#define KMAIN_SMEM (KMAIN_FLOATS * 4)

__global__ __launch_bounds__(512) void k_main(
    const float* __restrict__ x,
    const float* __restrict__ ln1w, const float* __restrict__ ln1b,
    const float* __restrict__ Wv, const float* __restrict__ bv,
    const float* __restrict__ Wp,
    const float* __restrict__ ln2w, const float* __restrict__ ln2b)
{
    extern __shared__ float sm[];
    float* pa    = sm + OFF_PA;
    float* scr   = sm + OFF_SCR;
    float* mu    = sm + OFF_MU;
    float* rsd   = sm + OFF_RSD;
    float* qt    = sm + OFF_QT;
    float* cc    = sm + OFF_CC;
    float* t0p   = sm + OFF_T0P;
    float* p0s   = sm + OFF_P0;
    float* mbars = sm + OFF_MB;
    float* red   = sm + OFF_RED2;

    const int b0  = blockIdx.x * BT;
    const int tid = threadIdx.x;
    const int w = tid >> 5, lane = tid & 31;

    if (tid < BT) { mu[tid * 50] = 0.f; rsd[tid * 50] = 0.f; }
    for (int idx = tid; idx < BT * 784; idx += 512) {
        int bt = idx / 784, r = idx % 784;
        int row = r / 28, col = r % 28;
        int pi = (row >> 2) * 7 + (col >> 2);
        int pp = (row & 3) * 4 + (col & 3);
        pa[bt * 784 + pi * 16 + pp] = x[(size_t)(b0 + bt) * 784 + r];
    }
    __syncthreads();

    for (int t = w * 2 + (lane >> 4); t < BT * 49; t += 32) {
        int bt = t / 49, sidx = t % 49, s = sidx + 1;
        int p = lane & 15;
        const float* pr = &pa[bt * 784 + sidx * 16];
        float pap = pr[p];
        float y = 0.f;
        #pragma unroll
        for (int q = 0; q < 16; q++) y += g_G[p * 16 + q] * pr[q];
        float e2p = pap * (y + 2.0f * g_hh[s * 16 + p]);
        float mup = pap * g_cs[p];
        #pragma unroll
        for (int o = 8; o > 0; o >>= 1) {
            e2p += __shfl_down_sync(0xffffffffu, e2p, o, 16);
            mup += __shfl_down_sync(0xffffffffu, mup, o, 16);
        }
        if (p == 0) {
            float m = (mup + g_pesum[s]) * (1.0f / (float)Dm);
            float var = (e2p + g_pesq[s]) * (1.0f / (float)Dm) - m * m;
            mu[bt * 50 + s] = m;
            rsd[bt * 50 + s] = rsqrtf(var + LNEPS);
        }
    }
    __syncthreads();

    for (int t = tid; t < BT * NH * SEQ; t += 512) {
        int bt = t / (NH * SEQ), rem = t % (NH * SEQ);
        int h = rem / SEQ, s = rem % SEQ;
        float v;
        if (s == 0) {
            v = g_sc0[h];
        } else {
            float g = g_pep[h * SEQ + s];
            const float* pr = &pa[bt * 784 + (s - 1) * 16];
            const float* vp = &g_vproj[h * 16];
            #pragma unroll
            for (int p = 0; p < 16; p++) g += pr[p] * vp[p];
            v = 32.0f * (rsd[bt * 50 + s] * (g - mu[bt * 50 + s] * g_su[h]) + g_gam[h]);
        }
        scr[bt * 832 + h * 52 + s] = v;
    }
    __syncthreads();

    for (int task = w; task < BT * NH; task += 16) {
        int bt = task >> 4, h = task & 15;
        float* row = &scr[bt * 832 + h * 52];
        float v1 = row[lane];
        float v2 = (lane + 32 < SEQ) ? row[lane + 32] : -INFINITY;
        float m = fmaxf(v1, v2);
        #pragma unroll
        for (int o = 16; o > 0; o >>= 1) m = fmaxf(m, __shfl_xor_sync(0xffffffffu, m, o));
        float e1 = expf(v1 - m);
        float e2 = (lane + 32 < SEQ) ? expf(v2 - m) : 0.f;
        float ss = e1 + e2;
        #pragma unroll
        for (int o = 16; o > 0; o >>= 1) ss += __shfl_xor_sync(0xffffffffu, ss, o);
        float inv = 1.0f / ss;
        float p1 = e1 * inv, p2 = e2 * inv;
        float r1 = (lane == 0) ? 0.f : p1 * rsd[bt * 50 + lane];
        float r2 = (lane + 32 < SEQ) ? p2 * rsd[bt * 50 + lane + 32] : 0.f;
        row[lane] = r1;
        if (lane + 32 < SEQ) row[lane + 32] = r2;
        float mb = r1 * mu[bt * 50 + lane]
                 + ((lane + 32 < SEQ) ? r2 * mu[bt * 50 + lane + 32] : 0.f);
        #pragma unroll
        for (int o = 16; o > 0; o >>= 1) mb += __shfl_xor_sync(0xffffffffu, mb, o);
        if (lane == 0) { mbars[bt * 16 + h] = mb; p0s[bt * 16 + h] = p1; }
    }
    __syncthreads();

    for (int task = w; task < BT * NH; task += 16) {
        int bt = task >> 4, h = task & 15;
        if (lane < 16) {
            int p = lane;
            const float* rr = &scr[bt * 832 + h * 52];
            const float* pb = &pa[bt * 784];
            float a = 0.f;
            #pragma unroll 7
            for (int sidx = 0; sidx < 49; sidx++)
                a += rr[sidx + 1] * pb[sidx * 16 + p];
            qt[bt * 256 + h * 16 + p] = a;
        }
    }
    __syncthreads();

    for (int gd = tid; gd < Dm; gd += 512) {
        int h = gd >> 6;
        float t1[BT], t2[BT];
        #pragma unroll
        for (int bt = 0; bt < BT; bt++) { t1[bt] = 0.f; t2[bt] = 0.f; }
        #pragma unroll
        for (int p = 0; p < 16; p++) {
            float wv = Wp[gd * 16 + p];
            #pragma unroll
            for (int bt = 0; bt < BT; bt++)
                t1[bt] += qt[bt * 256 + h * 16 + p] * wv;
        }
        #pragma unroll 7
        for (int s = 1; s < SEQ; s++) {
            float pev = g_pe[s * Dm + gd];
            #pragma unroll
            for (int bt = 0; bt < BT; bt++)
                t2[bt] += scr[bt * 832 + h * 52 + s] * pev;
        }
        float w1 = ln1w[gd], bb = ln1b[gd], xx0 = g_x0[gd];
        #pragma unroll
        for (int bt = 0; bt < BT; bt++) {
            float p0 = p0s[bt * 16 + h];
            cc[bt * 1024 + gd] = w1 * (t1[bt] + t2[bt] - mbars[bt * 16 + h])
                               + (1.0f - p0) * bb + p0 * xx0;
        }
    }
    __syncthreads();

    for (int ge = tid; ge < Dm; ge += 512) {
        int h = ge >> 6;
        float a[BT];
        float bve = bv[ge];
        #pragma unroll
        for (int bt = 0; bt < BT; bt++) a[bt] = bve;
        const float* wr = &Wv[(size_t)ge * DHd];
        #pragma unroll 8
        for (int d = 0; d < DHd; d++) {
            float wvd = wr[d];
            #pragma unroll
            for (int bt = 0; bt < BT; bt++)
                a[bt] += wvd * cc[bt * 1024 + h * DHd + d];
        }
        float tk0 = g_tok0[ge];
        #pragma unroll
        for (int bt = 0; bt < BT; bt++)
            t0p[bt * 1024 + ge] = tk0 + a[bt];
    }
    __syncthreads();

    for (int bt = 0; bt < BT; bt++) {
        float v0 = t0p[bt * 1024 + tid], v1 = t0p[bt * 1024 + tid + 512];
        float s = bred_generic(v0 + v1, red, 16);
        float m = s * (1.0f / (float)Dm);
        float d0 = v0 - m, d1 = v1 - m;
        float q = bred_generic(d0 * d0 + d1 * d1, red, 16);
        float rstd = rsqrtf(q * (1.0f / (float)Dm) + LNEPS);
        size_t base = (size_t)(b0 + bt) * Dm;
        g_tok0p[base + tid]       = v0;
        g_tok0p[base + tid + 512] = v1;
        g_n0[base + tid]       = d0 * rstd * ln2w[tid] + ln2b[tid];
        g_n0[base + tid + 512] = d1 * rstd * ln2w[tid + 512] + ln2b[tid + 512];
    }
}

// ============================================================================
// Tensor-core GEMM (3xTF32): C = A*Bw^T + bias (+Res).
// 64x64 CTA tile, 4 warps (32x32 each), BK=16. m16n8k8 tf32 mma.sync.
// ============================================================================
__device__ __forceinline__ uint32_t f2tf32(float x) {
    uint32_t r;
    asm("cvt.rna.tf32.f32 %0, %1;" : "=r"(r) : "f"(x));
    return r;
}

__device__ __forceinline__ void mma_tf32(float c[4], const uint32_t a[4],
                                         const uint32_t b[2]) {
    asm volatile(
        "mma.sync.aligned.m16n8k8.row.col.f32.tf32.tf32.f32 "
        "{%0,%1,%2,%3}, {%4,%5,%6,%7}, {%8,%9}, {%0,%1,%2,%3};\n"
        : "+f"(c[0]), "+f"(c[1]), "+f"(c[2]), "+f"(c[3])
        : "r"(a[0]), "r"(a[1]), "r"(a[2]), "r"(a[3]), "r"(b[0]), "r"(b[1]));
}

template <bool HAS_RES>
__global__ __launch_bounds__(128) void gemm_tc(
    const float* __restrict__ A, const float* __restrict__ Bw,
    const float* __restrict__ bias, const float* __restrict__ Res,
    float* __restrict__ C, int M, int N, int K)
{
    __shared__ float Ahs[16][72], Als[16][72], Bhs[16][72], Bls[16][72];
    const int tid = threadIdx.x;
    const int warp = tid >> 5, lane = tid & 31;
    const int wm = (warp & 1) * 32, wn = (warp >> 1) * 32;
    const int m0 = blockIdx.y * 64, n0 = blockIdx.x * 64;
    const int gid = lane >> 2, tg = lane & 3;

    float c[2][4][4];
    #pragma unroll
    for (int i = 0; i < 2; i++)
        #pragma unroll
        for (int j = 0; j < 4; j++)
            #pragma unroll
            for (int q = 0; q < 4; q++) c[i][j][q] = 0.f;

    const int lr = tid >> 1;        // 0..63 (row within tile)
    const int lk = (tid & 1) * 8;   // k offset 0 / 8
    const float* Ap = &A[(size_t)(m0 + lr) * K + lk];
    const int nr = n0 + lr;
    const float* Bp = &Bw[(size_t)(nr < N ? nr : 0) * K + lk];
    const bool bok = (nr < N);

    for (int k0 = 0; k0 < K; k0 += 16) {
        float4 a0 = *(const float4*)(Ap + k0);
        float4 a1 = *(const float4*)(Ap + k0 + 4);
        float4 b0 = make_float4(0.f, 0.f, 0.f, 0.f);
        float4 b1 = make_float4(0.f, 0.f, 0.f, 0.f);
        if (bok) {
            b0 = *(const float4*)(Bp + k0);
            b1 = *(const float4*)(Bp + k0 + 4);
        }
        __syncthreads();   // previous iteration's compute done
        {
            float af[8] = {a0.x, a0.y, a0.z, a0.w, a1.x, a1.y, a1.z, a1.w};
            float bf[8] = {b0.x, b0.y, b0.z, b0.w, b1.x, b1.y, b1.z, b1.w};
            #pragma unroll
            for (int i = 0; i < 8; i++) {
                float ha = __uint_as_float(f2tf32(af[i]));
                Ahs[lk + i][lr] = ha;
                Als[lk + i][lr] = __uint_as_float(f2tf32(af[i] - ha));
                float hb = __uint_as_float(f2tf32(bf[i]));
                Bhs[lk + i][lr] = hb;
                Bls[lk + i][lr] = __uint_as_float(f2tf32(bf[i] - hb));
            }
        }
        __syncthreads();
        #pragma unroll
        for (int ks = 0; ks < 16; ks += 8) {
            uint32_t ah[2][4], al[2][4], bh[4][2], bl[4][2];
            #pragma unroll
            for (int i = 0; i < 2; i++) {
                int m = wm + i * 16 + gid;
                ah[i][0] = __float_as_uint(Ahs[ks + tg][m]);
                ah[i][1] = __float_as_uint(Ahs[ks + tg][m + 8]);
                ah[i][2] = __float_as_uint(Ahs[ks + tg + 4][m]);
                ah[i][3] = __float_as_uint(Ahs[ks + tg + 4][m + 8]);
                al[i][0] = __float_as_uint(Als[ks + tg][m]);
                al[i][1] = __float_as_uint(Als[ks + tg][m + 8]);
                al[i][2] = __float_as_uint(Als[ks + tg + 4][m]);
                al[i][3] = __float_as_uint(Als[ks + tg + 4][m + 8]);
            }
            #pragma unroll
            for (int j = 0; j < 4; j++) {
                int n = wn + j * 8 + gid;
                bh[j][0] = __float_as_uint(Bhs[ks + tg][n]);
                bh[j][1] = __float_as_uint(Bhs[ks + tg + 4][n]);
                bl[j][0] = __float_as_uint(Bls[ks + tg][n]);
                bl[j][1] = __float_as_uint(Bls[ks + tg + 4][n]);
            }
            #pragma unroll
            for (int i = 0; i < 2; i++)
                #pragma unroll
                for (int j = 0; j < 4; j++) {
                    mma_tf32(c[i][j], ah[i], bh[j]);
                    mma_tf32(c[i][j], ah[i], bl[j]);
                    mma_tf32(c[i][j], al[i], bh[j]);
                }
        }
    }

    // epilogue
    #pragma unroll
    for (int i = 0; i < 2; i++) {
        #pragma unroll
        for (int j = 0; j < 4; j++) {
            int row0 = m0 + wm + i * 16 + gid;
            int col0 = n0 + wn + j * 8 + 2 * tg;
            #pragma unroll
            for (int q = 0; q < 4; q++) {
                int row = row0 + (q >> 1) * 8;
                int col = col0 + (q & 1);
                if (col < N) {
                    float v = c[i][j][q] + bias[col];
                    if (HAS_RES) v += Res[(size_t)row * N + col];
                    C[(size_t)row * N + col] = v;
                }
            }
        }
    }
}

// ---------------- softmax over 1000 logits -----------------------------------
__global__ __launch_bounds__(256) void softmax_kernel(float* __restrict__ out) {
    int b = blockIdx.x, tid = threadIdx.x;
    __shared__ float red[32];
    int lane = tid & 31, w = tid >> 5;
    float v[4];
    float m = -INFINITY;
    #pragma unroll
    for (int u = 0; u < 4; u++) {
        int j = tid + 256 * u;
        v[u] = (j < NOUT) ? out[(size_t)b * NOUT + j] : -INFINITY;
        m = fmaxf(m, v[u]);
    }
    #pragma unroll
    for (int o = 16; o > 0; o >>= 1) m = fmaxf(m, __shfl_xor_sync(0xffffffffu, m, o));
    if (lane == 0) red[w] = m;
    __syncthreads();
    if (tid < 8) {
        float x2 = red[tid];
        #pragma unroll
        for (int o = 4; o > 0; o >>= 1) x2 = fmaxf(x2, __shfl_xor_sync(0xffu, x2, o));
        if (tid == 0) red[0] = x2;
    }
    __syncthreads();
    m = red[0];
    __syncthreads();
    float s = 0.f;
    #pragma unroll
    for (int u = 0; u < 4; u++) {
        int j = tid + 256 * u;
        if (j < NOUT) { v[u] = expf(v[u] - m); s += v[u]; }
    }
    #pragma unroll
    for (int o = 16; o > 0; o >>= 1) s += __shfl_xor_sync(0xffffffffu, s, o);
    if (lane == 0) red[w] = s;
    __syncthreads();
    if (tid < 8) {
        float x2 = red[tid];
        #pragma unroll
        for (int o = 4; o > 0; o >>= 1) x2 += __shfl_xor_sync(0xffu, x2, o);
        if (tid == 0) red[0] = x2;
    }
    __syncthreads();
    float inv = 1.0f / red[0];
    #pragma unroll
    for (int u = 0; u < 4; u++) {
        int j = tid + 256 * u;
        if (j < NOUT) out[(size_t)b * NOUT + j] = v[u] * inv;
    }
}

// ---------------- launch ------------------------------------------------------
extern "C" void kernel_launch(void* const* d_in, const int* in_sizes, int n_in,
                              void* d_out, int out_size) {
    const float* x    = (const float*)d_in[0];
    const float* cls  = (const float*)d_in[1];
    const float* Wp   = (const float*)d_in[2];
    const float* ln1w = (const float*)d_in[3];
    const float* ln1b = (const float*)d_in[4];
    const float* Wq   = (const float*)d_in[5];
    const float* bq   = (const float*)d_in[6];
    const float* Wk   = (const float*)d_in[7];
    const float* bk   = (const float*)d_in[8];
    const float* Wv   = (const float*)d_in[9];
    const float* bv   = (const float*)d_in[10];
    const float* ln2w = (const float*)d_in[11];
    const float* ln2b = (const float*)d_in[12];
    const float* Wm   = (const float*)d_in[13];
    const float* bm   = (const float*)d_in[14];
    const float* Wh   = (const float*)d_in[15];
    const float* bh   = (const float*)d_in[16];
    float* out = (float*)d_out;

    float *p_n0 = nullptr, *p_tok0p = nullptr, *p_final = nullptr;
    cudaGetSymbolAddress((void**)&p_n0, g_n0);
    cudaGetSymbolAddress((void**)&p_tok0p, g_tok0p);
    cudaGetSymbolAddress((void**)&p_final, g_final);

    cudaFuncSetAttribute(k_main, cudaFuncAttributeMaxDynamicSharedMemorySize,
                         KMAIN_SMEM);

    k_pre<<<83, 256>>>(Wp, cls, ln1w, ln1b, Wq, bq, Wk, bk);
    k_main<<<Bsz / BT, 512, KMAIN_SMEM>>>(x, ln1w, ln1b, Wv, bv, Wp, ln2w, ln2b);
    gemm_tc<true><<<dim3(16, 16), 128>>>(
        p_n0, Wm, bm, p_tok0p, p_final, Bsz, Dm, Dm);
    gemm_tc<false><<<dim3(16, 16), 128>>>(
        p_final, Wh, bh, nullptr, out, Bsz, NOUT, Dm);
    softmax_kernel<<<Bsz, 256>>>(out);
}